// round 14
// baseline (speedup 1.0000x reference)
#include <cuda_runtime.h>
#include <cuda_fp16.h>
#include <math.h>
#include <stdint.h>

#define NHEADS 16
#define HDIM   128
#define CHUNK  64
#define BATCH  4
#define SEQ    4096
#define HID    2048
#define MROWS  (BATCH*SEQ)            /* 16384 */
#define QKV    (NHEADS*HDIM)          /* 2048  */

// ---------------- scratch (device globals; no allocation allowed) -----------
static __device__ __half g_q  [(size_t)MROWS*QKV];
static __device__ __half g_k  [(size_t)MROWS*QKV];
static __device__ __half g_v  [(size_t)MROWS*QKV];
static __device__ __half g_og [(size_t)MROWS*QKV];
static __device__ float  g_beta[(size_t)MROWS*NHEADS];
static __device__ __half g_a1 [(size_t)MROWS*HID];     // fp16 activations
static __device__ __half g_wq [(size_t)QKV*HID];
static __device__ __half g_wk [(size_t)QKV*HID];
static __device__ __half g_wv [(size_t)QKV*HID];
static __device__ __half g_wog[(size_t)QKV*HID];
static __device__ __half g_wo [(size_t)QKV*HID];

// ---------------- PTX helpers (family-PTX-safe: sm_80/90-era only) ----------
__device__ __forceinline__ uint32_t smem_u32(const void* p) {
    uint32_t a;
    asm("{ .reg .u64 t; cvta.to.shared.u64 t, %1; cvt.u32.u64 %0, t; }"
        : "=r"(a) : "l"(p));
    return a;
}
__device__ __forceinline__ void cpa16(uint32_t d, const void* s) {
    asm volatile("cp.async.cg.shared.global [%0], [%1], 16;" :: "r"(d), "l"(s));
}
__device__ __forceinline__ void mbar_init(uint32_t a, uint32_t cnt) {
    asm volatile("mbarrier.init.shared.b64 [%0], %1;" :: "r"(a), "r"(cnt) : "memory");
}
__device__ __forceinline__ void mbar_arrive(uint32_t a) {
    asm volatile("mbarrier.arrive.shared.b64 _, [%0];" :: "r"(a) : "memory");
}
__device__ __forceinline__ void mbar_wait(uint32_t a, uint32_t par) {
    asm volatile(
        "{\n\t.reg .pred P;\n\t"
        "W%=:\n\t"
        "mbarrier.try_wait.parity.shared.b64 P, [%0], %1, 0x989680;\n\t"
        "@!P bra W%=;\n\t}"
        :: "r"(a), "r"(par) : "memory");
}
__device__ __forceinline__ void cpa_mbar_arrive(uint32_t a) {
    asm volatile("cp.async.mbarrier.arrive.noinc.shared.b64 [%0];"
                 :: "r"(a) : "memory");
}
__device__ __forceinline__ void ldsm4(uint32_t& r0, uint32_t& r1,
                                      uint32_t& r2, uint32_t& r3, uint32_t a) {
    asm volatile("ldmatrix.sync.aligned.m8n8.x4.shared.b16 {%0,%1,%2,%3}, [%4];"
                 : "=r"(r0), "=r"(r1), "=r"(r2), "=r"(r3) : "r"(a));
}
__device__ __forceinline__ void mma16816(float* c, const uint32_t* a,
                                         uint32_t b0, uint32_t b1) {
    asm volatile(
        "mma.sync.aligned.m16n8k16.row.col.f32.f16.f16.f32 "
        "{%0,%1,%2,%3}, {%4,%5,%6,%7}, {%8,%9}, {%0,%1,%2,%3};"
        : "+f"(c[0]), "+f"(c[1]), "+f"(c[2]), "+f"(c[3])
        : "r"(a[0]), "r"(a[1]), "r"(a[2]), "r"(a[3]), "r"(b0), "r"(b1));
}

// typed pair-store: fp32 or fp16 output
__device__ __forceinline__ void st2(float* p, float x, float y) {
    *(float2*)p = make_float2(x, y);
}
__device__ __forceinline__ void st2(__half* p, float x, float y) {
    *(__half2*)p = __floats2half2_rn(x, y);
}

// ---------------------------------------------------------------------------
// Warp-specialized mma.sync fp16 GEMM: C[M,2048] = A @ W^T (+bias)
// 320 threads: 8 compute warps (warp tile 64x32, identical MMA order to R13)
// + 2 loader warps (warp 8: A tile, warp 9: W tile).
// 3 stages x 32KB; producer/consumer via mbarriers; NO __syncthreads in loop.
//   full[s]:  count 64  (loader threads, cp.async.mbarrier.arrive.noinc)
//   empty[s]: count 256 (compute threads, mbarrier.arrive)
// Stage s used by chunks sc with sc%3==s; usage index u=sc/3.
//   compute waits full[s]  parity  u&1
//   loader  waits empty[s] parity (u-1)&1   (skipped for sc<3)
// ---------------------------------------------------------------------------
#define NSC        32
#define OFF_A      0
#define OFF_W      16384
#define STG_BYTES  32768
#define GSMEM_DATA (3*STG_BYTES)          /* 98304 */
#define MB_FULL(s)  (GSMEM_DATA + (s)*8)
#define MB_EMPTY(s) (GSMEM_DATA + 24 + (s)*8)
#define GSMEM_T    (GSMEM_DATA + 48)

template <typename OutT>
__global__ __launch_bounds__(320, 1)
void gemm_f16(const __half* __restrict__ A, const __half* __restrict__ W,
              const float* __restrict__ bias, OutT* __restrict__ C)
{
    extern __shared__ __align__(1024) char smem[];
    const uint32_t sb = smem_u32(smem);
    const int tid = threadIdx.x;
    const int bn0 = blockIdx.x * 128;
    const int bm0 = blockIdx.y * 128;
    const size_t rowHB = (size_t)HID * 2;   // 4096 B row stride (A and W)

    if (tid == 0) {
#pragma unroll
        for (int s = 0; s < 3; s++) {
            mbar_init(sb + MB_FULL(s), 64);
            mbar_init(sb + MB_EMPTY(s), 256);
        }
    }
    __syncthreads();

    if (tid >= 256) {
        // ---------------- loader warps ----------------
        const int lt  = tid - 256;           // 0..63
        const int l   = lt & 31;
        const bool isA = (lt < 32);
        const int r0  = l >> 3;              // 0..3
        const int c16 = (l & 7) * 16;
        const char* gbase = (isA ? (const char*)A + (size_t)bm0 * rowHB
                                 : (const char*)W + (size_t)bn0 * rowHB) + c16;
        const uint32_t smoff = sb + (isA ? OFF_A : OFF_W);

        for (int sc = 0; sc < NSC; sc++) {
            const int s = sc - (sc / 3) * 3;
            const int u = sc / 3;
            if (sc >= 3) mbar_wait(sb + MB_EMPTY(s), (u - 1) & 1);
            const uint32_t st = smoff + s * STG_BYTES;
            const char* gp = gbase + (size_t)sc * 128;
#pragma unroll 8
            for (int i = 0; i < 32; i++) {
                const int row = i * 4 + r0;
                uint32_t off = (uint32_t)row * 128 + (uint32_t)c16;
                uint32_t sw  = off ^ ((off >> 3) & 0x70);
                cpa16(st + sw, gp + (size_t)row * rowHB);
            }
            cpa_mbar_arrive(sb + MB_FULL(s));
        }
        return;
    }

    // ---------------- compute warps (8 warps, 256 threads) ----------------
    const int lane = tid & 31;
    const int warp = tid >> 5;
    const int wm = warp >> 2;            // 0..1
    const int wn = warp & 3;             // 0..3

    const int a_row  = wm * 64 + (lane & 15);
    const int a_sel  = (lane >> 4) * 16;
    const uint32_t a_x = (uint32_t)((a_row & 7) << 4);
    const int b_row  = wn * 32 + ((lane >> 4) << 3) + (lane & 7);
    const int b_sel  = ((lane >> 3) & 1) * 16;
    const uint32_t b_x = (uint32_t)((b_row & 7) << 4);

    float acc[4][4][4];
#pragma unroll
    for (int i = 0; i < 4; i++)
#pragma unroll
        for (int j = 0; j < 4; j++)
#pragma unroll
            for (int r = 0; r < 4; r++) acc[i][j][r] = 0.0f;

    for (int sc = 0; sc < NSC; sc++) {
        const int s = sc - (sc / 3) * 3;
        const int u = sc / 3;
        mbar_wait(sb + MB_FULL(s), u & 1);

        const uint32_t st = sb + s * STG_BYTES;

#pragma unroll
        for (int ks = 0; ks < 4; ks++) {
            const uint32_t kb = (uint32_t)(ks * 32);
            uint32_t b[2][4];
#pragma unroll
            for (int nb = 0; nb < 2; nb++) {
                uint32_t broff = (uint32_t)(b_row + nb * 16) * 128
                               + ((kb + (uint32_t)b_sel) ^ b_x);
                ldsm4(b[nb][0], b[nb][1], b[nb][2], b[nb][3], st + OFF_W + broff);
            }
#pragma unroll
            for (int mf = 0; mf < 4; mf++) {
                uint32_t aroff = (uint32_t)(a_row + mf * 16) * 128
                               + ((kb + (uint32_t)a_sel) ^ a_x);
                uint32_t a[4];
                ldsm4(a[0], a[1], a[2], a[3], st + OFF_A + aroff);
                mma16816(acc[mf][0], a, b[0][0], b[0][1]);
                mma16816(acc[mf][1], a, b[0][2], b[0][3]);
                mma16816(acc[mf][2], a, b[1][0], b[1][1]);
                mma16816(acc[mf][3], a, b[1][2], b[1][3]);
            }
        }
        mbar_arrive(sb + MB_EMPTY(s));
    }

    // ---- epilogue (compute warps only) ----
#pragma unroll
    for (int nf = 0; nf < 4; nf++) {
        const int col = bn0 + wn * 32 + nf * 8 + (lane & 3) * 2;
        float b0 = 0.0f, b1 = 0.0f;
        if (bias) { b0 = bias[col]; b1 = bias[col + 1]; }
#pragma unroll
        for (int mf = 0; mf < 4; mf++) {
            const int row = bm0 + wm * 64 + mf * 16 + (lane >> 2);
            st2(C + (size_t)row * QKV + col,       acc[mf][nf][0] + b0,
                                                   acc[mf][nf][1] + b1);
            st2(C + (size_t)(row + 8) * QKV + col, acc[mf][nf][2] + b0,
                                                   acc[mf][nf][3] + b1);
        }
    }
}

// ---------------------------------------------------------------------------
__device__ __forceinline__ uint2 pack4h(float x, float y, float z, float w) {
    __half2 a = __floats2half2_rn(x, y);
    __half2 b = __floats2half2_rn(z, w);
    uint2 r;
    r.x = *(uint32_t*)&a;
    r.y = *(uint32_t*)&b;
    return r;
}

// all 5 weight matrices fp32 -> fp16 in one launch (blockIdx.y selects tensor)
__global__ __launch_bounds__(256)
void wconv5(const float* __restrict__ w0, const float* __restrict__ w1,
            const float* __restrict__ w2, const float* __restrict__ w3,
            const float* __restrict__ w4,
            __half* __restrict__ o0, __half* __restrict__ o1,
            __half* __restrict__ o2, __half* __restrict__ o3,
            __half* __restrict__ o4)
{
    const float* in;
    __half* out;
    switch (blockIdx.y) {
        case 0: in = w0; out = o0; break;
        case 1: in = w1; out = o1; break;
        case 2: in = w2; out = o2; break;
        case 3: in = w3; out = o3; break;
        default: in = w4; out = o4; break;
    }
    size_t i = ((size_t)blockIdx.x * 256 + threadIdx.x) * 4;
    float4 v = *(const float4*)(in + i);
    *(uint2*)(out + i) = pack4h(v.x, v.y, v.z, v.w);
}

// ---------------------------------------------------------------------------
// beta = hs @ b_w^T + b_b  (N=16), fp32; ALSO emits fp16 copy of hs.
// ---------------------------------------------------------------------------
__global__ __launch_bounds__(256)
void beta_gemm(const float* __restrict__ hs, const float* __restrict__ bw,
               const float* __restrict__ bb, float* __restrict__ beta,
               __half* __restrict__ a16)
{
    int warp = (blockIdx.x * blockDim.x + threadIdx.x) >> 5;
    int lane = threadIdx.x & 31;
    if (warp >= MROWS) return;
    const float* x = hs + (size_t)warp * HID;
    __half* xo = a16 + (size_t)warp * HID;

    float acc[NHEADS];
#pragma unroll
    for (int j = 0; j < NHEADS; j++) acc[j] = 0.0f;

    for (int t = 0; t < HID / 128; t++) {
        int k = t * 128 + lane * 4;
        float4 xv = *(const float4*)(x + k);
        *(uint2*)(xo + k) = pack4h(xv.x, xv.y, xv.z, xv.w);
#pragma unroll
        for (int j = 0; j < NHEADS; j++) {
            float4 wv = *(const float4*)(bw + (size_t)j * HID + k);
            acc[j] += xv.x*wv.x + xv.y*wv.y + xv.z*wv.z + xv.w*wv.w;
        }
    }
#pragma unroll
    for (int j = 0; j < NHEADS; j++)
#pragma unroll
        for (int off = 16; off > 0; off >>= 1)
            acc[j] += __shfl_xor_sync(0xffffffffu, acc[j], off);

    if (lane < NHEADS) {
        float v = 0.0f;
#pragma unroll
        for (int j = 0; j < NHEADS; j++) if (lane == j) v = acc[j];
        beta[(size_t)warp * NHEADS + lane] = v + bb[lane];
    }
}

// ---------------------------------------------------------------------------
// Chunk attention (unchanged from R13): HMMA phase-2 with fp32 post-scale,
// fp32 phase-3, fused l2norm / softplus / silu gate, fp16 activation out.
// ---------------------------------------------------------------------------
#define ATT_KS     17408
#define ATT_FQ     34816
#define ATT_FK     35072
#define ATT_S      35328
#define ATT_SMEM   52736
#define QROW_B     272

__global__ __launch_bounds__(256)
void attn_kernel(const __half* __restrict__ q, const __half* __restrict__ k,
                 const __half* __restrict__ v, const __half* __restrict__ og,
                 const float* __restrict__ beta, __half* __restrict__ outa)
{
    extern __shared__ __align__(1024) char smraw[];
    float* fq  = (float*)(smraw + ATT_FQ);
    float* fk  = (float*)(smraw + ATT_FK);
    float* S   = (float*)(smraw + ATT_S);
    float* gvS = (float*)smraw;
    const uint32_t qsB = smem_u32(smraw);
    const uint32_t ksB = qsB + ATT_KS;

    const int h  = blockIdx.x;
    const int cn = blockIdx.y;
    const int b  = blockIdx.z;
    const int tid = threadIdx.x;
    const int lane = tid & 31;
    const int warp = tid >> 5;

    const size_t tok0 = (size_t)b * SEQ + (size_t)cn * CHUNK;
    const size_t base = (tok0 * NHEADS + h) * HDIM;
    const int tokstride = NHEADS * HDIM;
    const float eps_n = 1.1313708499e-11f;

    for (int f = tid; f < 64 * 32; f += 256) {
        int row = f >> 5;
        int l8  = f & 31;
        size_t g = base + (size_t)row * tokstride + l8 * 4;
        uint2 qr = *(const uint2*)(q + g);
        uint2 kr = *(const uint2*)(k + g);

        float2 q01 = __half22float2(*(__half2*)&qr.x);
        float2 q23 = __half22float2(*(__half2*)&qr.y);
        float2 k01 = __half22float2(*(__half2*)&kr.x);
        float2 k23 = __half22float2(*(__half2*)&kr.y);
        float sq = q01.x*q01.x + q01.y*q01.y + q23.x*q23.x + q23.y*q23.y;
        float sk = k01.x*k01.x + k01.y*k01.y + k23.x*k23.x + k23.y*k23.y;
#pragma unroll
        for (int off = 16; off > 0; off >>= 1) {
            sq += __shfl_xor_sync(0xffffffffu, sq, off);
            sk += __shfl_xor_sync(0xffffffffu, sk, off);
        }
        *(uint2*)(smraw + row * QROW_B + l8 * 8)          = qr;
        *(uint2*)(smraw + ATT_KS + row * QROW_B + l8 * 8) = kr;
        if (lane == 0) {
            fq[row] = 1.0f / fmaxf(sqrtf(sq), eps_n);
            fk[row] = 1.0f / fmaxf(sqrtf(sk), eps_n);
        }
    }
    __syncthreads();

    {
        const int m0 = (warp >> 1) * 16;
        const int n0 = (warp & 1) * 32;
        if (n0 > m0 + 15) {
            for (int idx = lane; idx < 512; idx += 32) {
                int r = m0 + (idx >> 5);
                int j = n0 + (idx & 31);
                S[r * 68 + j] = 0.0f;
            }
        } else {
            float acc[4][4];
#pragma unroll
            for (int t = 0; t < 4; t++)
#pragma unroll
                for (int r = 0; r < 4; r++) acc[t][r] = 0.0f;

            const uint32_t aoff = qsB + (uint32_t)(m0 + (lane & 15)) * QROW_B
                                + (uint32_t)((lane >> 4) * 16);
            const int brow = n0 + ((lane >> 4) << 3) + (lane & 7);
            const uint32_t boff0 = ksB + (uint32_t)brow * QROW_B
                                 + (uint32_t)(((lane >> 3) & 1) * 16);
            const uint32_t boff1 = boff0 + 16u * QROW_B;

#pragma unroll
            for (int ks = 0; ks < 8; ks++) {
                const uint32_t kb = (uint32_t)(ks * 32);
                uint32_t a[4], b0[4], b1[4];
                ldsm4(a[0], a[1], a[2], a[3], aoff + kb);
                ldsm4(b0[0], b0[1], b0[2], b0[3], boff0 + kb);
                ldsm4(b1[0], b1[1], b1[2], b1[3], boff1 + kb);
                mma16816(acc[0], a, b0[0], b0[1]);
                mma16816(acc[1], a, b0[2], b0[3]);
                mma16816(acc[2], a, b1[0], b1[1]);
                mma16816(acc[3], a, b1[2], b1[3]);
            }

            const int r0 = m0 + (lane >> 2);
            const int r1 = r0 + 8;
            const float fq0 = fq[r0], fq1 = fq[r1];
#pragma unroll
            for (int t = 0; t < 4; t++) {
                const int j0 = n0 + t * 8 + (lane & 3) * 2;
                const int j1 = j0 + 1;
                const float fk0 = fk[j0], fk1 = fk[j1];
                S[r0 * 68 + j0] = (j0 <= r0) ? acc[t][0] * fq0 * fk0 : 0.0f;
                S[r0 * 68 + j1] = (j1 <= r0) ? acc[t][1] * fq0 * fk1 : 0.0f;
                S[r1 * 68 + j0] = (j0 <= r1) ? acc[t][2] * fq1 * fk0 : 0.0f;
                S[r1 * 68 + j1] = (j1 <= r1) ? acc[t][3] * fq1 * fk1 : 0.0f;
            }
        }
    }
    __syncthreads();

    for (int f = tid; f < 64 * 32; f += 256) {
        int row = f >> 5;
        int c4  = (f & 31) << 2;
        float bta = beta[(tok0 + row) * NHEADS + h];
        float sp  = (bta > 20.0f) ? bta : log1pf(expf(bta));
        uint2 vr = *(const uint2*)(v + base + (size_t)row * tokstride + c4);
        float2 v01 = __half22float2(*(__half2*)&vr.x);
        float2 v23 = __half22float2(*(__half2*)&vr.y);
        float4 vv = make_float4(v01.x * sp, v01.y * sp, v23.x * sp, v23.y * sp);
        *(float4*)&gvS[row * 128 + c4] = vv;
    }
    __syncthreads();

    {
        const int tx = tid & 15, ty = tid >> 4;
        const int kk0 = tx * 8, i0 = ty * 4;
        float o[4][8] = {};
        const int jend = i0 + 4;
        for (int j = 0; j < jend; j++) {
            float s0 = S[(i0+0)*68 + j];
            float s1 = S[(i0+1)*68 + j];
            float s2 = S[(i0+2)*68 + j];
            float s3 = S[(i0+3)*68 + j];
            float4 g0 = *(const float4*)&gvS[j * 128 + kk0];
            float4 g1 = *(const float4*)&gvS[j * 128 + kk0 + 4];
            const float gg[8] = {g0.x,g0.y,g0.z,g0.w,g1.x,g1.y,g1.z,g1.w};
#pragma unroll
            for (int n = 0; n < 8; n++) {
                o[0][n] += s0 * gg[n];
                o[1][n] += s1 * gg[n];
                o[2][n] += s2 * gg[n];
                o[3][n] += s3 * gg[n];
            }
        }
#pragma unroll
        for (int m = 0; m < 4; m++) {
            const size_t roff = base + (size_t)(i0 + m) * tokstride + kk0;
            uint2 ogr0 = *(const uint2*)(og + roff);
            uint2 ogr1 = *(const uint2*)(og + roff + 4);
            float2 ga = __half22float2(*(__half2*)&ogr0.x);
            float2 gb = __half22float2(*(__half2*)&ogr0.y);
            float2 gc = __half22float2(*(__half2*)&ogr1.x);
            float2 gd = __half22float2(*(__half2*)&ogr1.y);
            const float gx[8] = {ga.x, ga.y, gb.x, gb.y, gc.x, gc.y, gd.x, gd.y};
            float y[8];
#pragma unroll
            for (int n = 0; n < 8; n++)
                y[n] = o[m][n] * (gx[n] / (1.0f + expf(-gx[n])));
            uint2 p0 = pack4h(y[0], y[1], y[2], y[3]);
            uint2 p1 = pack4h(y[4], y[5], y[6], y[7]);
            *(uint2*)(outa + roff)     = p0;
            *(uint2*)(outa + roff + 4) = p1;
        }
    }
}

// ---------------------------------------------------------------------------
extern "C" void kernel_launch(void* const* d_in, const int* in_sizes, int n_in,
                              void* d_out, int out_size)
{
    const float* hs   = (const float*)d_in[0];
    const float* q_w  = (const float*)d_in[1];
    const float* q_b  = (const float*)d_in[2];
    const float* k_w  = (const float*)d_in[3];
    const float* k_b  = (const float*)d_in[4];
    const float* v_w  = (const float*)d_in[5];
    const float* v_b  = (const float*)d_in[6];
    /* a_w, a_b (d_in[7], d_in[8]) are dead code in the reference */
    const float* b_w  = (const float*)d_in[9];
    const float* b_b  = (const float*)d_in[10];
    const float* og_w = (const float*)d_in[11];
    const float* o_w  = (const float*)d_in[12];
    const float* o_b  = (const float*)d_in[13];
    float* out = (float*)d_out;

    float *gbeta;
    __half *gq, *gk, *gv, *gog, *ga1, *gwq, *gwk, *gwv, *gwog, *gwo;
    cudaGetSymbolAddress((void**)&gq,    g_q);
    cudaGetSymbolAddress((void**)&gk,    g_k);
    cudaGetSymbolAddress((void**)&gv,    g_v);
    cudaGetSymbolAddress((void**)&gog,   g_og);
    cudaGetSymbolAddress((void**)&gbeta, g_beta);
    cudaGetSymbolAddress((void**)&ga1,   g_a1);
    cudaGetSymbolAddress((void**)&gwq,   g_wq);
    cudaGetSymbolAddress((void**)&gwk,   g_wk);
    cudaGetSymbolAddress((void**)&gwv,   g_wv);
    cudaGetSymbolAddress((void**)&gwog,  g_wog);
    cudaGetSymbolAddress((void**)&gwo,   g_wo);

    cudaFuncSetAttribute(gemm_f16<__half>,
                         cudaFuncAttributeMaxDynamicSharedMemorySize, GSMEM_T);
    cudaFuncSetAttribute(gemm_f16<float>,
                         cudaFuncAttributeMaxDynamicSharedMemorySize, GSMEM_T);
    cudaFuncSetAttribute(attn_kernel,
                         cudaFuncAttributeMaxDynamicSharedMemorySize, ATT_SMEM);

    const dim3 gG(QKV / 128, MROWS / 128);        // (16, 128)
    const unsigned wBlocks = (unsigned)((size_t)QKV * HID / 4 / 256);   // 4096

    // launch 0: beta GEMM + fused fp16 activation convert
    beta_gemm<<<MROWS / 8, 256>>>(hs, b_w, b_b, gbeta, ga1);

    // launch 1: all 5 weight converts
    wconv5<<<dim3(wBlocks, 5), 256>>>(q_w, k_w, v_w, og_w, o_w,
                                      gwq, gwk, gwv, gwog, gwo);

    // launches 2-5: projection GEMMs (fp16 outputs), warp-specialized
    gemm_f16<__half><<<gG, 320, GSMEM_T>>>(ga1, gwq,  q_b,    gq);
    gemm_f16<__half><<<gG, 320, GSMEM_T>>>(ga1, gwk,  k_b,    gk);
    gemm_f16<__half><<<gG, 320, GSMEM_T>>>(ga1, gwv,  v_b,    gv);
    gemm_f16<__half><<<gG, 320, GSMEM_T>>>(ga1, gwog, nullptr, gog);

    // launch 6: fused attention (HMMA phase-2, fp32 phase-3, silu gate)
    dim3 gAttn(NHEADS, SEQ / CHUNK, BATCH);
    attn_kernel<<<gAttn, 256, ATT_SMEM>>>(gq, gk, gv, gog, gbeta, ga1);

    // launch 7: output projection (fp32 out)
    gemm_f16<float><<<gG, 320, GSMEM_T>>>(ga1, gwo, o_b, out);
}

// round 15
// speedup vs baseline: 1.2227x; 1.2227x over previous
#include <cuda_runtime.h>
#include <cuda_fp16.h>
#include <math.h>
#include <stdint.h>

#define NHEADS 16
#define HDIM   128
#define CHUNK  64
#define BATCH  4
#define SEQ    4096
#define HID    2048
#define MROWS  (BATCH*SEQ)            /* 16384 */
#define QKV    (NHEADS*HDIM)          /* 2048  */
#define WPLANE ((size_t)QKV*HID)      /* weight plane elems  */
#define CPLANE ((size_t)MROWS*QKV)    /* output plane elems  */

// ---------------- scratch (device globals; no allocation allowed) -----------
static __device__ __half g_proj[4*CPLANE];            // q,k,v,og planes
static __device__ float  g_beta[(size_t)MROWS*NHEADS];
static __device__ __half g_a1 [(size_t)MROWS*HID];    // fp16 activations
static __device__ __half g_wall[5*WPLANE];            // qw,kw,vw,ogw,ow planes

struct BiasPack { const float* p[4]; };

// ---------------- PTX helpers (family-PTX-safe: sm_80/90-era only) ----------
__device__ __forceinline__ uint32_t smem_u32(const void* p) {
    uint32_t a;
    asm("{ .reg .u64 t; cvta.to.shared.u64 t, %1; cvt.u32.u64 %0, t; }"
        : "=r"(a) : "l"(p));
    return a;
}
__device__ __forceinline__ void cpa16(uint32_t d, const void* s) {
    asm volatile("cp.async.cg.shared.global [%0], [%1], 16;" :: "r"(d), "l"(s));
}
__device__ __forceinline__ void mbar_init(uint32_t a, uint32_t cnt) {
    asm volatile("mbarrier.init.shared.b64 [%0], %1;" :: "r"(a), "r"(cnt) : "memory");
}
__device__ __forceinline__ void mbar_arrive(uint32_t a) {
    asm volatile("mbarrier.arrive.shared.b64 _, [%0];" :: "r"(a) : "memory");
}
__device__ __forceinline__ void mbar_wait(uint32_t a, uint32_t par) {
    asm volatile(
        "{\n\t.reg .pred P;\n\t"
        "W%=:\n\t"
        "mbarrier.try_wait.parity.shared.b64 P, [%0], %1, 0x989680;\n\t"
        "@!P bra W%=;\n\t}"
        :: "r"(a), "r"(par) : "memory");
}
__device__ __forceinline__ void cpa_mbar_arrive(uint32_t a) {
    asm volatile("cp.async.mbarrier.arrive.noinc.shared.b64 [%0];"
                 :: "r"(a) : "memory");
}
__device__ __forceinline__ void ldsm4(uint32_t& r0, uint32_t& r1,
                                      uint32_t& r2, uint32_t& r3, uint32_t a) {
    asm volatile("ldmatrix.sync.aligned.m8n8.x4.shared.b16 {%0,%1,%2,%3}, [%4];"
                 : "=r"(r0), "=r"(r1), "=r"(r2), "=r"(r3) : "r"(a));
}
__device__ __forceinline__ void mma16816(float* c, const uint32_t* a,
                                         uint32_t b0, uint32_t b1) {
    asm volatile(
        "mma.sync.aligned.m16n8k16.row.col.f32.f16.f16.f32 "
        "{%0,%1,%2,%3}, {%4,%5,%6,%7}, {%8,%9}, {%0,%1,%2,%3};"
        : "+f"(c[0]), "+f"(c[1]), "+f"(c[2]), "+f"(c[3])
        : "r"(a[0]), "r"(a[1]), "r"(a[2]), "r"(a[3]), "r"(b0), "r"(b1));
}

// typed pair-store: fp32 or fp16 output
__device__ __forceinline__ void st2(float* p, float x, float y) {
    *(float2*)p = make_float2(x, y);
}
__device__ __forceinline__ void st2(__half* p, float x, float y) {
    *(__half2*)p = __floats2half2_rn(x, y);
}

// ---------------------------------------------------------------------------
// mma.sync fp16 GEMM: C_z[M,2048] = A @ W_z^T (+bias_z), z = blockIdx.z plane.
// CTA tile 128x128, 256 threads (8 warps, warp tile 64x32, R13 MMA order).
// 3 stages x 32KB; full/empty mbarrier flow control (NO __syncthreads in
// mainloop); loads issued by the same warps AFTER their MMAs -> warps may
// drift ~1 chunk instead of rendezvousing. 2 CTAs/SM (128 regs x 256 thr).
//   full[s]  count 256: cp.async.mbarrier.arrive.noinc per thread
//   empty[s] count 256: mbarrier.arrive per thread after consuming
//   stage s usage u = sc/3: wait full parity u&1; producer waits
//   empty[s2] parity (u2-1)&1 before reloading (skipped for sl<3).
// ---------------------------------------------------------------------------
#define NSC        32
#define OFF_A      0
#define OFF_W      16384
#define STG_BYTES  32768
#define GSMEM_DATA (3*STG_BYTES)
#define MB_FULL(s)  (GSMEM_DATA + (s)*8)
#define MB_EMPTY(s) (GSMEM_DATA + 24 + (s)*8)
#define GSMEM_T    (GSMEM_DATA + 48)

template <typename OutT>
__global__ __launch_bounds__(256, 2)
void gemm_f16(const __half* __restrict__ A, const __half* __restrict__ Wall,
              BiasPack bp, OutT* __restrict__ Call)
{
    extern __shared__ __align__(1024) char smem[];
    const uint32_t sb = smem_u32(smem);
    const int tid = threadIdx.x;
    const int z   = blockIdx.z;
    const int bn0 = blockIdx.x * 128;
    const int bm0 = blockIdx.y * 128;
    const __half* W = Wall + (size_t)z * WPLANE;
    OutT* C = Call + (size_t)z * CPLANE;
    const float* bias = bp.p[z];
    const size_t rowHB = (size_t)HID * 2;

    if (tid == 0) {
#pragma unroll
        for (int s = 0; s < 3; s++) {
            mbar_init(sb + MB_FULL(s), 256);
            mbar_init(sb + MB_EMPTY(s), 256);
        }
    }
    __syncthreads();

    // ---- loader geometry (all warps) ----
    const int r0  = tid >> 3;             // 0..31
    const int c16 = (tid & 7) * 16;
    const char* abase = (const char*)A + (size_t)bm0 * rowHB + c16;
    const char* wbase = (const char*)W + (size_t)bn0 * rowHB + c16;

    auto load_stage = [&](int sc, int s) {
        const uint32_t st = sb + s * STG_BYTES;
        const char* ap = abase + (size_t)sc * 128;
        const char* wp = wbase + (size_t)sc * 128;
#pragma unroll
        for (int i = 0; i < 4; i++) {
            const int row = r0 + i * 32;
            uint32_t off = (uint32_t)row * 128 + (uint32_t)c16;
            uint32_t sw  = off ^ ((off >> 3) & 0x70);
            cpa16(st + OFF_A + sw, ap + (size_t)row * rowHB);
            cpa16(st + OFF_W + sw, wp + (size_t)row * rowHB);
        }
        cpa_mbar_arrive(sb + MB_FULL(s));
    };

    // ---- warp fragment geometry (identical to R13) ----
    const int lane = tid & 31;
    const int warp = tid >> 5;
    const int wm = warp >> 2;
    const int wn = warp & 3;

    const int a_row  = wm * 64 + (lane & 15);
    const int a_sel  = (lane >> 4) * 16;
    const uint32_t a_x = (uint32_t)((a_row & 7) << 4);
    const int b_row  = wn * 32 + ((lane >> 4) << 3) + (lane & 7);
    const int b_sel  = ((lane >> 3) & 1) * 16;
    const uint32_t b_x = (uint32_t)((b_row & 7) << 4);

    float acc[4][4][4];
#pragma unroll
    for (int i = 0; i < 4; i++)
#pragma unroll
        for (int j = 0; j < 4; j++)
#pragma unroll
            for (int r = 0; r < 4; r++) acc[i][j][r] = 0.0f;

    // prologue: stages 0,1
    load_stage(0, 0);
    load_stage(1, 1);

    for (int sc = 0; sc < NSC; sc++) {
        const int s = sc - (sc / 3) * 3;
        const int u = sc / 3;
        mbar_wait(sb + MB_FULL(s), u & 1);

        const uint32_t st = sb + s * STG_BYTES;
#pragma unroll
        for (int ks = 0; ks < 4; ks++) {
            const uint32_t kb = (uint32_t)(ks * 32);
            uint32_t b[2][4];
#pragma unroll
            for (int nb = 0; nb < 2; nb++) {
                uint32_t broff = (uint32_t)(b_row + nb * 16) * 128
                               + ((kb + (uint32_t)b_sel) ^ b_x);
                ldsm4(b[nb][0], b[nb][1], b[nb][2], b[nb][3], st + OFF_W + broff);
            }
#pragma unroll
            for (int mf = 0; mf < 4; mf++) {
                uint32_t aroff = (uint32_t)(a_row + mf * 16) * 128
                               + ((kb + (uint32_t)a_sel) ^ a_x);
                uint32_t a[4];
                ldsm4(a[0], a[1], a[2], a[3], st + OFF_A + aroff);
                mma16816(acc[mf][0], a, b[0][0], b[0][1]);
                mma16816(acc[mf][1], a, b[0][2], b[0][3]);
                mma16816(acc[mf][2], a, b[1][0], b[1][1]);
                mma16816(acc[mf][3], a, b[1][2], b[1][3]);
            }
        }
        mbar_arrive(sb + MB_EMPTY(s));

        const int sl = sc + 2;
        if (sl < NSC) {
            const int s2 = sl - (sl / 3) * 3;
            const int u2 = sl / 3;
            if (sl >= 3) mbar_wait(sb + MB_EMPTY(s2), (u2 - 1) & 1);
            load_stage(sl, s2);
        }
    }

    // ---- epilogue ----
#pragma unroll
    for (int nf = 0; nf < 4; nf++) {
        const int col = bn0 + wn * 32 + nf * 8 + (lane & 3) * 2;
        float b0 = 0.0f, b1 = 0.0f;
        if (bias) { b0 = bias[col]; b1 = bias[col + 1]; }
#pragma unroll
        for (int mf = 0; mf < 4; mf++) {
            const int row = bm0 + wm * 64 + mf * 16 + (lane >> 2);
            st2(C + (size_t)row * QKV + col,       acc[mf][nf][0] + b0,
                                                   acc[mf][nf][1] + b1);
            st2(C + (size_t)(row + 8) * QKV + col, acc[mf][nf][2] + b0,
                                                   acc[mf][nf][3] + b1);
        }
    }
}

// ---------------------------------------------------------------------------
__device__ __forceinline__ uint2 pack4h(float x, float y, float z, float w) {
    __half2 a = __floats2half2_rn(x, y);
    __half2 b = __floats2half2_rn(z, w);
    uint2 r;
    r.x = *(uint32_t*)&a;
    r.y = *(uint32_t*)&b;
    return r;
}

// all 5 weight matrices fp32 -> fp16 planes of g_wall (blockIdx.y = plane)
__global__ __launch_bounds__(256)
void wconv5(const float* __restrict__ w0, const float* __restrict__ w1,
            const float* __restrict__ w2, const float* __restrict__ w3,
            const float* __restrict__ w4, __half* __restrict__ wall)
{
    const float* in;
    switch (blockIdx.y) {
        case 0: in = w0; break;
        case 1: in = w1; break;
        case 2: in = w2; break;
        case 3: in = w3; break;
        default: in = w4; break;
    }
    __half* out = wall + (size_t)blockIdx.y * WPLANE;
    size_t i = ((size_t)blockIdx.x * 256 + threadIdx.x) * 4;
    float4 v = *(const float4*)(in + i);
    *(uint2*)(out + i) = pack4h(v.x, v.y, v.z, v.w);
}

// ---------------------------------------------------------------------------
// beta = hs @ b_w^T + b_b  (N=16), fp32; ALSO emits fp16 copy of hs.
// ---------------------------------------------------------------------------
__global__ __launch_bounds__(256)
void beta_gemm(const float* __restrict__ hs, const float* __restrict__ bw,
               const float* __restrict__ bb, float* __restrict__ beta,
               __half* __restrict__ a16)
{
    int warp = (blockIdx.x * blockDim.x + threadIdx.x) >> 5;
    int lane = threadIdx.x & 31;
    if (warp >= MROWS) return;
    const float* x = hs + (size_t)warp * HID;
    __half* xo = a16 + (size_t)warp * HID;

    float acc[NHEADS];
#pragma unroll
    for (int j = 0; j < NHEADS; j++) acc[j] = 0.0f;

    for (int t = 0; t < HID / 128; t++) {
        int k = t * 128 + lane * 4;
        float4 xv = *(const float4*)(x + k);
        *(uint2*)(xo + k) = pack4h(xv.x, xv.y, xv.z, xv.w);
#pragma unroll
        for (int j = 0; j < NHEADS; j++) {
            float4 wv = *(const float4*)(bw + (size_t)j * HID + k);
            acc[j] += xv.x*wv.x + xv.y*wv.y + xv.z*wv.z + xv.w*wv.w;
        }
    }
#pragma unroll
    for (int j = 0; j < NHEADS; j++)
#pragma unroll
        for (int off = 16; off > 0; off >>= 1)
            acc[j] += __shfl_xor_sync(0xffffffffu, acc[j], off);

    if (lane < NHEADS) {
        float v = 0.0f;
#pragma unroll
        for (int j = 0; j < NHEADS; j++) if (lane == j) v = acc[j];
        beta[(size_t)warp * NHEADS + lane] = v + bb[lane];
    }
}

// ---------------------------------------------------------------------------
// Chunk attention (R13): HMMA phase-2 with fp32 post-scale, fp32 phase-3,
// fused l2norm / softplus / silu gate, fp16 activation out.
// ---------------------------------------------------------------------------
#define ATT_KS     17408
#define ATT_FQ     34816
#define ATT_FK     35072
#define ATT_S      35328
#define ATT_SMEM   52736
#define QROW_B     272

__global__ __launch_bounds__(256)
void attn_kernel(const __half* __restrict__ q, const __half* __restrict__ k,
                 const __half* __restrict__ v, const __half* __restrict__ og,
                 const float* __restrict__ beta, __half* __restrict__ outa)
{
    extern __shared__ __align__(1024) char smraw[];
    float* fq  = (float*)(smraw + ATT_FQ);
    float* fk  = (float*)(smraw + ATT_FK);
    float* S   = (float*)(smraw + ATT_S);
    float* gvS = (float*)smraw;
    const uint32_t qsB = smem_u32(smraw);
    const uint32_t ksB = qsB + ATT_KS;

    const int h  = blockIdx.x;
    const int cn = blockIdx.y;
    const int b  = blockIdx.z;
    const int tid = threadIdx.x;
    const int lane = tid & 31;
    const int warp = tid >> 5;

    const size_t tok0 = (size_t)b * SEQ + (size_t)cn * CHUNK;
    const size_t base = (tok0 * NHEADS + h) * HDIM;
    const int tokstride = NHEADS * HDIM;
    const float eps_n = 1.1313708499e-11f;

    for (int f = tid; f < 64 * 32; f += 256) {
        int row = f >> 5;
        int l8  = f & 31;
        size_t g = base + (size_t)row * tokstride + l8 * 4;
        uint2 qr = *(const uint2*)(q + g);
        uint2 kr = *(const uint2*)(k + g);

        float2 q01 = __half22float2(*(__half2*)&qr.x);
        float2 q23 = __half22float2(*(__half2*)&qr.y);
        float2 k01 = __half22float2(*(__half2*)&kr.x);
        float2 k23 = __half22float2(*(__half2*)&kr.y);
        float sq = q01.x*q01.x + q01.y*q01.y + q23.x*q23.x + q23.y*q23.y;
        float sk = k01.x*k01.x + k01.y*k01.y + k23.x*k23.x + k23.y*k23.y;
#pragma unroll
        for (int off = 16; off > 0; off >>= 1) {
            sq += __shfl_xor_sync(0xffffffffu, sq, off);
            sk += __shfl_xor_sync(0xffffffffu, sk, off);
        }
        *(uint2*)(smraw + row * QROW_B + l8 * 8)          = qr;
        *(uint2*)(smraw + ATT_KS + row * QROW_B + l8 * 8) = kr;
        if (lane == 0) {
            fq[row] = 1.0f / fmaxf(sqrtf(sq), eps_n);
            fk[row] = 1.0f / fmaxf(sqrtf(sk), eps_n);
        }
    }
    __syncthreads();

    {
        const int m0 = (warp >> 1) * 16;
        const int n0 = (warp & 1) * 32;
        if (n0 > m0 + 15) {
            for (int idx = lane; idx < 512; idx += 32) {
                int r = m0 + (idx >> 5);
                int j = n0 + (idx & 31);
                S[r * 68 + j] = 0.0f;
            }
        } else {
            float acc[4][4];
#pragma unroll
            for (int t = 0; t < 4; t++)
#pragma unroll
                for (int r = 0; r < 4; r++) acc[t][r] = 0.0f;

            const uint32_t aoff = qsB + (uint32_t)(m0 + (lane & 15)) * QROW_B
                                + (uint32_t)((lane >> 4) * 16);
            const int brow = n0 + ((lane >> 4) << 3) + (lane & 7);
            const uint32_t boff0 = ksB + (uint32_t)brow * QROW_B
                                 + (uint32_t)(((lane >> 3) & 1) * 16);
            const uint32_t boff1 = boff0 + 16u * QROW_B;

#pragma unroll
            for (int ks = 0; ks < 8; ks++) {
                const uint32_t kb = (uint32_t)(ks * 32);
                uint32_t a[4], b0[4], b1[4];
                ldsm4(a[0], a[1], a[2], a[3], aoff + kb);
                ldsm4(b0[0], b0[1], b0[2], b0[3], boff0 + kb);
                ldsm4(b1[0], b1[1], b1[2], b1[3], boff1 + kb);
                mma16816(acc[0], a, b0[0], b0[1]);
                mma16816(acc[1], a, b0[2], b0[3]);
                mma16816(acc[2], a, b1[0], b1[1]);
                mma16816(acc[3], a, b1[2], b1[3]);
            }

            const int r0 = m0 + (lane >> 2);
            const int r1 = r0 + 8;
            const float fq0 = fq[r0], fq1 = fq[r1];
#pragma unroll
            for (int t = 0; t < 4; t++) {
                const int j0 = n0 + t * 8 + (lane & 3) * 2;
                const int j1 = j0 + 1;
                const float fk0 = fk[j0], fk1 = fk[j1];
                S[r0 * 68 + j0] = (j0 <= r0) ? acc[t][0] * fq0 * fk0 : 0.0f;
                S[r0 * 68 + j1] = (j1 <= r0) ? acc[t][1] * fq0 * fk1 : 0.0f;
                S[r1 * 68 + j0] = (j0 <= r1) ? acc[t][2] * fq1 * fk0 : 0.0f;
                S[r1 * 68 + j1] = (j1 <= r1) ? acc[t][3] * fq1 * fk1 : 0.0f;
            }
        }
    }
    __syncthreads();

    for (int f = tid; f < 64 * 32; f += 256) {
        int row = f >> 5;
        int c4  = (f & 31) << 2;
        float bta = beta[(tok0 + row) * NHEADS + h];
        float sp  = (bta > 20.0f) ? bta : log1pf(expf(bta));
        uint2 vr = *(const uint2*)(v + base + (size_t)row * tokstride + c4);
        float2 v01 = __half22float2(*(__half2*)&vr.x);
        float2 v23 = __half22float2(*(__half2*)&vr.y);
        float4 vv = make_float4(v01.x * sp, v01.y * sp, v23.x * sp, v23.y * sp);
        *(float4*)&gvS[row * 128 + c4] = vv;
    }
    __syncthreads();

    {
        const int tx = tid & 15, ty = tid >> 4;
        const int kk0 = tx * 8, i0 = ty * 4;
        float o[4][8] = {};
        const int jend = i0 + 4;
        for (int j = 0; j < jend; j++) {
            float s0 = S[(i0+0)*68 + j];
            float s1 = S[(i0+1)*68 + j];
            float s2 = S[(i0+2)*68 + j];
            float s3 = S[(i0+3)*68 + j];
            float4 g0 = *(const float4*)&gvS[j * 128 + kk0];
            float4 g1 = *(const float4*)&gvS[j * 128 + kk0 + 4];
            const float gg[8] = {g0.x,g0.y,g0.z,g0.w,g1.x,g1.y,g1.z,g1.w};
#pragma unroll
            for (int n = 0; n < 8; n++) {
                o[0][n] += s0 * gg[n];
                o[1][n] += s1 * gg[n];
                o[2][n] += s2 * gg[n];
                o[3][n] += s3 * gg[n];
            }
        }
#pragma unroll
        for (int m = 0; m < 4; m++) {
            const size_t roff = base + (size_t)(i0 + m) * tokstride + kk0;
            uint2 ogr0 = *(const uint2*)(og + roff);
            uint2 ogr1 = *(const uint2*)(og + roff + 4);
            float2 ga = __half22float2(*(__half2*)&ogr0.x);
            float2 gb = __half22float2(*(__half2*)&ogr0.y);
            float2 gc = __half22float2(*(__half2*)&ogr1.x);
            float2 gd = __half22float2(*(__half2*)&ogr1.y);
            const float gx[8] = {ga.x, ga.y, gb.x, gb.y, gc.x, gc.y, gd.x, gd.y};
            float y[8];
#pragma unroll
            for (int n = 0; n < 8; n++)
                y[n] = o[m][n] * (gx[n] / (1.0f + expf(-gx[n])));
            uint2 p0 = pack4h(y[0], y[1], y[2], y[3]);
            uint2 p1 = pack4h(y[4], y[5], y[6], y[7]);
            *(uint2*)(outa + roff)     = p0;
            *(uint2*)(outa + roff + 4) = p1;
        }
    }
}

// ---------------------------------------------------------------------------
extern "C" void kernel_launch(void* const* d_in, const int* in_sizes, int n_in,
                              void* d_out, int out_size)
{
    const float* hs   = (const float*)d_in[0];
    const float* q_w  = (const float*)d_in[1];
    const float* q_b  = (const float*)d_in[2];
    const float* k_w  = (const float*)d_in[3];
    const float* k_b  = (const float*)d_in[4];
    const float* v_w  = (const float*)d_in[5];
    const float* v_b  = (const float*)d_in[6];
    /* a_w, a_b (d_in[7], d_in[8]) are dead code in the reference */
    const float* b_w  = (const float*)d_in[9];
    const float* b_b  = (const float*)d_in[10];
    const float* og_w = (const float*)d_in[11];
    const float* o_w  = (const float*)d_in[12];
    const float* o_b  = (const float*)d_in[13];
    float* out = (float*)d_out;

    float *gbeta;
    __half *gproj, *ga1, *gwall;
    cudaGetSymbolAddress((void**)&gproj, g_proj);
    cudaGetSymbolAddress((void**)&gbeta, g_beta);
    cudaGetSymbolAddress((void**)&ga1,   g_a1);
    cudaGetSymbolAddress((void**)&gwall, g_wall);

    cudaFuncSetAttribute(gemm_f16<__half>,
                         cudaFuncAttributeMaxDynamicSharedMemorySize, GSMEM_T);
    cudaFuncSetAttribute(gemm_f16<float>,
                         cudaFuncAttributeMaxDynamicSharedMemorySize, GSMEM_T);
    cudaFuncSetAttribute(attn_kernel,
                         cudaFuncAttributeMaxDynamicSharedMemorySize, ATT_SMEM);

    const unsigned wBlocks = (unsigned)(WPLANE / 4 / 256);   // 4096

    // launch 0: beta GEMM + fused fp16 activation convert
    beta_gemm<<<MROWS / 8, 256>>>(hs, b_w, b_b, gbeta, ga1);

    // launch 1: all 5 weight converts into g_wall planes
    wconv5<<<dim3(wBlocks, 5), 256>>>(q_w, k_w, v_w, og_w, o_w, gwall);

    // launch 2: all 4 projection GEMMs in one launch (grid.z = plane)
    BiasPack bp4;
    bp4.p[0] = q_b; bp4.p[1] = k_b; bp4.p[2] = v_b; bp4.p[3] = nullptr;
    dim3 gG4(QKV / 128, MROWS / 128, 4);          // (16, 128, 4)
    gemm_f16<__half><<<gG4, 256, GSMEM_T>>>(ga1, gwall, bp4, gproj);

    // launch 3: fused attention (HMMA phase-2, fp32 phase-3, silu gate)
    dim3 gAttn(NHEADS, SEQ / CHUNK, BATCH);
    attn_kernel<<<gAttn, 256, ATT_SMEM>>>(gproj,              // q plane
                                          gproj + CPLANE,     // k plane
                                          gproj + 2*CPLANE,   // v plane
                                          gproj + 3*CPLANE,   // og plane
                                          gbeta, ga1);

    // launch 4: output projection (fp32 out, weight plane 4)
    BiasPack bpo;
    bpo.p[0] = o_b; bpo.p[1] = bpo.p[2] = bpo.p[3] = nullptr;
    dim3 gGo(QKV / 128, MROWS / 128, 1);
    gemm_f16<float><<<gGo, 256, GSMEM_T>>>(ga1, gwall + 4*WPLANE, bpo, out);
}

// round 16
// speedup vs baseline: 1.2577x; 1.0287x over previous
#include <cuda_runtime.h>
#include <cuda_fp16.h>
#include <math.h>
#include <stdint.h>

#define NHEADS 16
#define HDIM   128
#define CHUNK  64
#define BATCH  4
#define SEQ    4096
#define HID    2048
#define MROWS  (BATCH*SEQ)            /* 16384 */
#define QKV    (NHEADS*HDIM)          /* 2048  */
#define WPLANE ((size_t)QKV*HID)
#define CPLANE ((size_t)MROWS*QKV)

// ---------------- scratch (device globals; no allocation allowed) -----------
static __device__ __half g_proj[4*CPLANE];            // q,k,v,og planes
static __device__ float  g_beta[(size_t)MROWS*NHEADS];
static __device__ __half g_a1 [(size_t)MROWS*HID];    // fp16 activations
static __device__ __half g_wall[5*WPLANE];            // qw,kw,vw,ogw,ow planes

struct BiasPack { const float* p[4]; };

// ---------------- PTX helpers (family-PTX-safe: sm_80/90-era only) ----------
__device__ __forceinline__ uint32_t smem_u32(const void* p) {
    uint32_t a;
    asm("{ .reg .u64 t; cvta.to.shared.u64 t, %1; cvt.u32.u64 %0, t; }"
        : "=r"(a) : "l"(p));
    return a;
}
__device__ __forceinline__ void cpa16(uint32_t d, const void* s) {
    asm volatile("cp.async.cg.shared.global [%0], [%1], 16;" :: "r"(d), "l"(s));
}
__device__ __forceinline__ void mbar_init(uint32_t a, uint32_t cnt) {
    asm volatile("mbarrier.init.shared.b64 [%0], %1;" :: "r"(a), "r"(cnt) : "memory");
}
__device__ __forceinline__ void mbar_arrive(uint32_t a) {
    asm volatile("mbarrier.arrive.shared.b64 _, [%0];" :: "r"(a) : "memory");
}
__device__ __forceinline__ void mbar_wait(uint32_t a, uint32_t par) {
    asm volatile(
        "{\n\t.reg .pred P;\n\t"
        "W%=:\n\t"
        "mbarrier.try_wait.parity.shared.b64 P, [%0], %1, 0x989680;\n\t"
        "@!P bra W%=;\n\t}"
        :: "r"(a), "r"(par) : "memory");
}
__device__ __forceinline__ void cpa_mbar_arrive(uint32_t a) {
    asm volatile("cp.async.mbarrier.arrive.noinc.shared.b64 [%0];"
                 :: "r"(a) : "memory");
}
__device__ __forceinline__ void ldsm4(uint32_t& r0, uint32_t& r1,
                                      uint32_t& r2, uint32_t& r3, uint32_t a) {
    asm volatile("ldmatrix.sync.aligned.m8n8.x4.shared.b16 {%0,%1,%2,%3}, [%4];"
                 : "=r"(r0), "=r"(r1), "=r"(r2), "=r"(r3) : "r"(a));
}
__device__ __forceinline__ void ldsm4t(uint32_t& r0, uint32_t& r1,
                                       uint32_t& r2, uint32_t& r3, uint32_t a) {
    asm volatile("ldmatrix.sync.aligned.m8n8.x4.trans.shared.b16 {%0,%1,%2,%3}, [%4];"
                 : "=r"(r0), "=r"(r1), "=r"(r2), "=r"(r3) : "r"(a));
}
__device__ __forceinline__ void mma16816(float* c, const uint32_t* a,
                                         uint32_t b0, uint32_t b1) {
    asm volatile(
        "mma.sync.aligned.m16n8k16.row.col.f32.f16.f16.f32 "
        "{%0,%1,%2,%3}, {%4,%5,%6,%7}, {%8,%9}, {%0,%1,%2,%3};"
        : "+f"(c[0]), "+f"(c[1]), "+f"(c[2]), "+f"(c[3])
        : "r"(a[0]), "r"(a[1]), "r"(a[2]), "r"(a[3]), "r"(b0), "r"(b1));
}

__device__ __forceinline__ void st2(float* p, float x, float y) {
    *(float2*)p = make_float2(x, y);
}
__device__ __forceinline__ void st2(__half* p, float x, float y) {
    *(__half2*)p = __floats2half2_rn(x, y);
}

// ---------------------------------------------------------------------------
// mma.sync fp16 GEMM (R15): 128x128 CTA tile, 256 thr, 3-stage mbarrier flow,
// 2 CTAs/SM, grid.z selects weight/bias/output plane.
// ---------------------------------------------------------------------------
#define NSC        32
#define OFF_A      0
#define OFF_W      16384
#define STG_BYTES  32768
#define GSMEM_DATA (3*STG_BYTES)
#define MB_FULL(s)  (GSMEM_DATA + (s)*8)
#define MB_EMPTY(s) (GSMEM_DATA + 24 + (s)*8)
#define GSMEM_T    (GSMEM_DATA + 48)

template <typename OutT>
__global__ __launch_bounds__(256, 2)
void gemm_f16(const __half* __restrict__ A, const __half* __restrict__ Wall,
              BiasPack bp, OutT* __restrict__ Call)
{
    extern __shared__ __align__(1024) char smem[];
    const uint32_t sb = smem_u32(smem);
    const int tid = threadIdx.x;
    const int z   = blockIdx.z;
    const int bn0 = blockIdx.x * 128;
    const int bm0 = blockIdx.y * 128;
    const __half* W = Wall + (size_t)z * WPLANE;
    OutT* C = Call + (size_t)z * CPLANE;
    const float* bias = bp.p[z];
    const size_t rowHB = (size_t)HID * 2;

    if (tid == 0) {
#pragma unroll
        for (int s = 0; s < 3; s++) {
            mbar_init(sb + MB_FULL(s), 256);
            mbar_init(sb + MB_EMPTY(s), 256);
        }
    }
    __syncthreads();

    const int r0  = tid >> 3;
    const int c16 = (tid & 7) * 16;
    const char* abase = (const char*)A + (size_t)bm0 * rowHB + c16;
    const char* wbase = (const char*)W + (size_t)bn0 * rowHB + c16;

    auto load_stage = [&](int sc, int s) {
        const uint32_t st = sb + s * STG_BYTES;
        const char* ap = abase + (size_t)sc * 128;
        const char* wp = wbase + (size_t)sc * 128;
#pragma unroll
        for (int i = 0; i < 4; i++) {
            const int row = r0 + i * 32;
            uint32_t off = (uint32_t)row * 128 + (uint32_t)c16;
            uint32_t sw  = off ^ ((off >> 3) & 0x70);
            cpa16(st + OFF_A + sw, ap + (size_t)row * rowHB);
            cpa16(st + OFF_W + sw, wp + (size_t)row * rowHB);
        }
        cpa_mbar_arrive(sb + MB_FULL(s));
    };

    const int lane = tid & 31;
    const int warp = tid >> 5;
    const int wm = warp >> 2;
    const int wn = warp & 3;

    const int a_row  = wm * 64 + (lane & 15);
    const int a_sel  = (lane >> 4) * 16;
    const uint32_t a_x = (uint32_t)((a_row & 7) << 4);
    const int b_row  = wn * 32 + ((lane >> 4) << 3) + (lane & 7);
    const int b_sel  = ((lane >> 3) & 1) * 16;
    const uint32_t b_x = (uint32_t)((b_row & 7) << 4);

    float acc[4][4][4];
#pragma unroll
    for (int i = 0; i < 4; i++)
#pragma unroll
        for (int j = 0; j < 4; j++)
#pragma unroll
            for (int r = 0; r < 4; r++) acc[i][j][r] = 0.0f;

    load_stage(0, 0);
    load_stage(1, 1);

    for (int sc = 0; sc < NSC; sc++) {
        const int s = sc - (sc / 3) * 3;
        const int u = sc / 3;
        mbar_wait(sb + MB_FULL(s), u & 1);

        const uint32_t st = sb + s * STG_BYTES;
#pragma unroll
        for (int ks = 0; ks < 4; ks++) {
            const uint32_t kb = (uint32_t)(ks * 32);
            uint32_t b[2][4];
#pragma unroll
            for (int nb = 0; nb < 2; nb++) {
                uint32_t broff = (uint32_t)(b_row + nb * 16) * 128
                               + ((kb + (uint32_t)b_sel) ^ b_x);
                ldsm4(b[nb][0], b[nb][1], b[nb][2], b[nb][3], st + OFF_W + broff);
            }
#pragma unroll
            for (int mf = 0; mf < 4; mf++) {
                uint32_t aroff = (uint32_t)(a_row + mf * 16) * 128
                               + ((kb + (uint32_t)a_sel) ^ a_x);
                uint32_t a[4];
                ldsm4(a[0], a[1], a[2], a[3], st + OFF_A + aroff);
                mma16816(acc[mf][0], a, b[0][0], b[0][1]);
                mma16816(acc[mf][1], a, b[0][2], b[0][3]);
                mma16816(acc[mf][2], a, b[1][0], b[1][1]);
                mma16816(acc[mf][3], a, b[1][2], b[1][3]);
            }
        }
        mbar_arrive(sb + MB_EMPTY(s));

        const int sl = sc + 2;
        if (sl < NSC) {
            const int s2 = sl - (sl / 3) * 3;
            const int u2 = sl / 3;
            if (sl >= 3) mbar_wait(sb + MB_EMPTY(s2), (u2 - 1) & 1);
            load_stage(sl, s2);
        }
    }

#pragma unroll
    for (int nf = 0; nf < 4; nf++) {
        const int col = bn0 + wn * 32 + nf * 8 + (lane & 3) * 2;
        float b0 = 0.0f, b1 = 0.0f;
        if (bias) { b0 = bias[col]; b1 = bias[col + 1]; }
#pragma unroll
        for (int mf = 0; mf < 4; mf++) {
            const int row = bm0 + wm * 64 + mf * 16 + (lane >> 2);
            st2(C + (size_t)row * QKV + col,       acc[mf][nf][0] + b0,
                                                   acc[mf][nf][1] + b1);
            st2(C + (size_t)(row + 8) * QKV + col, acc[mf][nf][2] + b0,
                                                   acc[mf][nf][3] + b1);
        }
    }
}

// ---------------------------------------------------------------------------
__device__ __forceinline__ uint2 pack4h(float x, float y, float z, float w) {
    __half2 a = __floats2half2_rn(x, y);
    __half2 b = __floats2half2_rn(z, w);
    uint2 r;
    r.x = *(uint32_t*)&a;
    r.y = *(uint32_t*)&b;
    return r;
}

// all 5 weight matrices fp32 -> fp16 planes of g_wall (blockIdx.y = plane)
__global__ __launch_bounds__(256)
void wconv5(const float* __restrict__ w0, const float* __restrict__ w1,
            const float* __restrict__ w2, const float* __restrict__ w3,
            const float* __restrict__ w4, __half* __restrict__ wall)
{
    const float* in;
    switch (blockIdx.y) {
        case 0: in = w0; break;
        case 1: in = w1; break;
        case 2: in = w2; break;
        case 3: in = w3; break;
        default: in = w4; break;
    }
    __half* out = wall + (size_t)blockIdx.y * WPLANE;
    size_t i = ((size_t)blockIdx.x * 256 + threadIdx.x) * 4;
    float4 v = *(const float4*)(in + i);
    *(uint2*)(out + i) = pack4h(v.x, v.y, v.z, v.w);
}

// ---------------------------------------------------------------------------
// beta = hs @ b_w^T + b_b  (N=16), fp32; ALSO emits fp16 copy of hs.
// ---------------------------------------------------------------------------
__global__ __launch_bounds__(256)
void beta_gemm(const float* __restrict__ hs, const float* __restrict__ bw,
               const float* __restrict__ bb, float* __restrict__ beta,
               __half* __restrict__ a16)
{
    int warp = (blockIdx.x * blockDim.x + threadIdx.x) >> 5;
    int lane = threadIdx.x & 31;
    if (warp >= MROWS) return;
    const float* x = hs + (size_t)warp * HID;
    __half* xo = a16 + (size_t)warp * HID;

    float acc[NHEADS];
#pragma unroll
    for (int j = 0; j < NHEADS; j++) acc[j] = 0.0f;

    for (int t = 0; t < HID / 128; t++) {
        int k = t * 128 + lane * 4;
        float4 xv = *(const float4*)(x + k);
        *(uint2*)(xo + k) = pack4h(xv.x, xv.y, xv.z, xv.w);
#pragma unroll
        for (int j = 0; j < NHEADS; j++) {
            float4 wv = *(const float4*)(bw + (size_t)j * HID + k);
            acc[j] += xv.x*wv.x + xv.y*wv.y + xv.z*wv.z + xv.w*wv.w;
        }
    }
#pragma unroll
    for (int j = 0; j < NHEADS; j++)
#pragma unroll
        for (int off = 16; off > 0; off >>= 1)
            acc[j] += __shfl_xor_sync(0xffffffffu, acc[j], off);

    if (lane < NHEADS) {
        float v = 0.0f;
#pragma unroll
        for (int j = 0; j < NHEADS; j++) if (lane == j) v = acc[j];
        beta[(size_t)warp * NHEADS + lane] = v + bb[lane];
    }
}

// ---------------------------------------------------------------------------
// Chunk attention v3: HMMA phase-2 (raw q.k + fp32 norm post-scale, fp16 S
// with tril zeros) AND HMMA phase-3 (S @ GV, both fp16, fp32 accumulate,
// k-steps beyond the diagonal block skipped). Fused l2norm/softplus/silu.
//   qT/GV region: [64][272B]   (raw fp16 q, later fp16 gv row-major [j][kk])
//   kT:           [64][272B]
//   fq/fk:        64 floats each
//   S16:          [64][144B]   fp16, bank-step-4 padded
// ---------------------------------------------------------------------------
#define ATT_KS     17408
#define ATT_FQ     34816
#define ATT_FK     35072
#define ATT_S16    35328
#define SROW_B     144
#define ATT_SMEM   (ATT_S16 + 64*SROW_B)   /* 44544 */
#define QROW_B     272

__global__ __launch_bounds__(256)
void attn_kernel(const __half* __restrict__ q, const __half* __restrict__ k,
                 const __half* __restrict__ v, const __half* __restrict__ og,
                 const float* __restrict__ beta, __half* __restrict__ outa)
{
    extern __shared__ __align__(1024) char smraw[];
    float* fq  = (float*)(smraw + ATT_FQ);
    float* fk  = (float*)(smraw + ATT_FK);
    const uint32_t qsB  = smem_u32(smraw);
    const uint32_t ksB  = qsB + ATT_KS;
    const uint32_t s16B = qsB + ATT_S16;

    const int h  = blockIdx.x;
    const int cn = blockIdx.y;
    const int b  = blockIdx.z;
    const int tid = threadIdx.x;
    const int lane = tid & 31;
    const int warp = tid >> 5;

    const size_t tok0 = (size_t)b * SEQ + (size_t)cn * CHUNK;
    const size_t base = (tok0 * NHEADS + h) * HDIM;
    const int tokstride = NHEADS * HDIM;
    const float eps_n = 1.1313708499e-11f;

    // ---- phase 1: raw fp16 q,k to padded smem; 1/norm via warp reduce ----
    for (int f = tid; f < 64 * 32; f += 256) {
        int row = f >> 5;
        int l8  = f & 31;
        size_t g = base + (size_t)row * tokstride + l8 * 4;
        uint2 qr = *(const uint2*)(q + g);
        uint2 kr = *(const uint2*)(k + g);

        float2 q01 = __half22float2(*(__half2*)&qr.x);
        float2 q23 = __half22float2(*(__half2*)&qr.y);
        float2 k01 = __half22float2(*(__half2*)&kr.x);
        float2 k23 = __half22float2(*(__half2*)&kr.y);
        float sq = q01.x*q01.x + q01.y*q01.y + q23.x*q23.x + q23.y*q23.y;
        float sk = k01.x*k01.x + k01.y*k01.y + k23.x*k23.x + k23.y*k23.y;
#pragma unroll
        for (int off = 16; off > 0; off >>= 1) {
            sq += __shfl_xor_sync(0xffffffffu, sq, off);
            sk += __shfl_xor_sync(0xffffffffu, sk, off);
        }
        *(uint2*)(smraw + row * QROW_B + l8 * 8)          = qr;
        *(uint2*)(smraw + ATT_KS + row * QROW_B + l8 * 8) = kr;
        if (lane == 0) {
            fq[row] = 1.0f / fmaxf(sqrtf(sq), eps_n);
            fk[row] = 1.0f / fmaxf(sqrtf(sk), eps_n);
        }
    }
    __syncthreads();

    // ---- phase 2: S16 = tril( (q.k) * fq_i * fk_j ) via HMMA, fp16 out ----
    {
        const int m0 = (warp >> 1) * 16;
        const int n0 = (warp & 1) * 32;
        if (n0 > m0 + 15) {
            // fully masked 16x32 tile: zero-fill (uint32 = 2 halves)
            for (int idx = lane; idx < 256; idx += 32) {
                int r  = m0 + (idx >> 4);
                int jp = n0 + (idx & 15) * 2;
                *(uint32_t*)(smraw + ATT_S16 + r * SROW_B + jp * 2) = 0u;
            }
        } else {
            float acc[4][4];
#pragma unroll
            for (int t = 0; t < 4; t++)
#pragma unroll
                for (int r = 0; r < 4; r++) acc[t][r] = 0.0f;

            const uint32_t aoff = qsB + (uint32_t)(m0 + (lane & 15)) * QROW_B
                                + (uint32_t)((lane >> 4) * 16);
            const int brow = n0 + ((lane >> 4) << 3) + (lane & 7);
            const uint32_t boff0 = ksB + (uint32_t)brow * QROW_B
                                 + (uint32_t)(((lane >> 3) & 1) * 16);
            const uint32_t boff1 = boff0 + 16u * QROW_B;

#pragma unroll
            for (int ks = 0; ks < 8; ks++) {
                const uint32_t kb = (uint32_t)(ks * 32);
                uint32_t a[4], b0[4], b1[4];
                ldsm4(a[0], a[1], a[2], a[3], aoff + kb);
                ldsm4(b0[0], b0[1], b0[2], b0[3], boff0 + kb);
                ldsm4(b1[0], b1[1], b1[2], b1[3], boff1 + kb);
                mma16816(acc[0], a, b0[0], b0[1]);
                mma16816(acc[1], a, b0[2], b0[3]);
                mma16816(acc[2], a, b1[0], b1[1]);
                mma16816(acc[3], a, b1[2], b1[3]);
            }

            const int r0s = m0 + (lane >> 2);
            const int r1s = r0s + 8;
            const float fq0 = fq[r0s], fq1 = fq[r1s];
#pragma unroll
            for (int t = 0; t < 4; t++) {
                const int j0 = n0 + t * 8 + (lane & 3) * 2;
                const int j1 = j0 + 1;
                const float fk0 = fk[j0], fk1 = fk[j1];
                float v00 = (j0 <= r0s) ? acc[t][0] * fq0 * fk0 : 0.0f;
                float v01 = (j1 <= r0s) ? acc[t][1] * fq0 * fk1 : 0.0f;
                float v10 = (j0 <= r1s) ? acc[t][2] * fq1 * fk0 : 0.0f;
                float v11 = (j1 <= r1s) ? acc[t][3] * fq1 * fk1 : 0.0f;
                *(__half2*)(smraw + ATT_S16 + r0s * SROW_B + j0 * 2) =
                    __floats2half2_rn(v00, v01);
                *(__half2*)(smraw + ATT_S16 + r1s * SROW_B + j0 * 2) =
                    __floats2half2_rn(v10, v11);
            }
        }
    }
    __syncthreads();   // S16 complete; qT ldsm reads done

    // ---- gv = softplus(beta) * v, fp16, into the qT region [j][kk] ----
    for (int f = tid; f < 64 * 32; f += 256) {
        int row = f >> 5;
        int l8  = f & 31;
        float bta = beta[(tok0 + row) * NHEADS + h];
        float sp  = (bta > 20.0f) ? bta : log1pf(expf(bta));
        uint2 vr = *(const uint2*)(v + base + (size_t)row * tokstride + l8 * 4);
        float2 v01 = __half22float2(*(__half2*)&vr.x);
        float2 v23 = __half22float2(*(__half2*)&vr.y);
        *(uint2*)(smraw + row * QROW_B + l8 * 8) =
            pack4h(v01.x * sp, v01.y * sp, v23.x * sp, v23.y * sp);
    }
    __syncthreads();

    // ---- phase 3: O = S16 @ GV via HMMA; gate with silu(og); fp16 out ----
    {
        const int mt = warp >> 1;          // 0..3 -> rows 16*mt..
        const int nh = warp & 1;           // 0..1 -> cols nh*64..
        float acc[8][4];
#pragma unroll
        for (int f = 0; f < 8; f++)
#pragma unroll
            for (int r = 0; r < 4; r++) acc[f][r] = 0.0f;

        for (int kst = 0; kst <= mt; kst++) {
            uint32_t a[4];
            uint32_t aaddr = s16B + (uint32_t)(16*mt + (lane & 15)) * SROW_B
                           + (uint32_t)(kst * 32 + (lane >> 4) * 16);
            ldsm4(a[0], a[1], a[2], a[3], aaddr);
#pragma unroll
            for (int g = 0; g < 4; g++) {
                const uint32_t brow = (uint32_t)(kst * 16
                                   + ((lane >> 3) & 1) * 8 + (lane & 7));
                const uint32_t bcol = (uint32_t)(nh * 64 + g * 16
                                   + (lane >> 4) * 8);
                uint32_t b[4];
                ldsm4t(b[0], b[1], b[2], b[3], qsB + brow * QROW_B + bcol * 2);
                mma16816(acc[g*2],   a, b[0], b[1]);
                mma16816(acc[g*2+1], a, b[2], b[3]);
            }
        }

        const int r0o = 16*mt + (lane >> 2);
        const int r1o = r0o + 8;
#pragma unroll
        for (int f = 0; f < 8; f++) {
            const int col = nh * 64 + (f >> 1) * 16 + (f & 1) * 8
                          + (lane & 3) * 2;
            size_t off0 = base + (size_t)r0o * tokstride + col;
            size_t off1 = base + (size_t)r1o * tokstride + col;
            float2 g0 = __half22float2(*(const __half2*)(og + off0));
            float2 g1 = __half22float2(*(const __half2*)(og + off1));
            float y0 = acc[f][0] * (g0.x / (1.0f + expf(-g0.x)));
            float y1 = acc[f][1] * (g0.y / (1.0f + expf(-g0.y)));
            float y2 = acc[f][2] * (g1.x / (1.0f + expf(-g1.x)));
            float y3 = acc[f][3] * (g1.y / (1.0f + expf(-g1.y)));
            *(__half2*)(outa + off0) = __floats2half2_rn(y0, y1);
            *(__half2*)(outa + off1) = __floats2half2_rn(y2, y3);
        }
    }
}

// ---------------------------------------------------------------------------
extern "C" void kernel_launch(void* const* d_in, const int* in_sizes, int n_in,
                              void* d_out, int out_size)
{
    const float* hs   = (const float*)d_in[0];
    const float* q_w  = (const float*)d_in[1];
    const float* q_b  = (const float*)d_in[2];
    const float* k_w  = (const float*)d_in[3];
    const float* k_b  = (const float*)d_in[4];
    const float* v_w  = (const float*)d_in[5];
    const float* v_b  = (const float*)d_in[6];
    /* a_w, a_b (d_in[7], d_in[8]) are dead code in the reference */
    const float* b_w  = (const float*)d_in[9];
    const float* b_b  = (const float*)d_in[10];
    const float* og_w = (const float*)d_in[11];
    const float* o_w  = (const float*)d_in[12];
    const float* o_b  = (const float*)d_in[13];
    float* out = (float*)d_out;

    float *gbeta;
    __half *gproj, *ga1, *gwall;
    cudaGetSymbolAddress((void**)&gproj, g_proj);
    cudaGetSymbolAddress((void**)&gbeta, g_beta);
    cudaGetSymbolAddress((void**)&ga1,   g_a1);
    cudaGetSymbolAddress((void**)&gwall, g_wall);

    cudaFuncSetAttribute(gemm_f16<__half>,
                         cudaFuncAttributeMaxDynamicSharedMemorySize, GSMEM_T);
    cudaFuncSetAttribute(gemm_f16<float>,
                         cudaFuncAttributeMaxDynamicSharedMemorySize, GSMEM_T);
    cudaFuncSetAttribute(attn_kernel,
                         cudaFuncAttributeMaxDynamicSharedMemorySize, ATT_SMEM);

    const unsigned wBlocks = (unsigned)(WPLANE / 4 / 256);   // 4096

    // launch 0: beta GEMM + fused fp16 activation convert
    beta_gemm<<<MROWS / 8, 256>>>(hs, b_w, b_b, gbeta, ga1);

    // launch 1: all 5 weight converts into g_wall planes
    wconv5<<<dim3(wBlocks, 5), 256>>>(q_w, k_w, v_w, og_w, o_w, gwall);

    // launch 2: all 4 projection GEMMs in one launch (grid.z = plane)
    BiasPack bp4;
    bp4.p[0] = q_b; bp4.p[1] = k_b; bp4.p[2] = v_b; bp4.p[3] = nullptr;
    dim3 gG4(QKV / 128, MROWS / 128, 4);
    gemm_f16<__half><<<gG4, 256, GSMEM_T>>>(ga1, gwall, bp4, gproj);

    // launch 3: fused attention (HMMA phase-2 AND phase-3)
    dim3 gAttn(NHEADS, SEQ / CHUNK, BATCH);
    attn_kernel<<<gAttn, 256, ATT_SMEM>>>(gproj,              // q plane
                                          gproj + CPLANE,     // k plane
                                          gproj + 2*CPLANE,   // v plane
                                          gproj + 3*CPLANE,   // og plane
                                          gbeta, ga1);

    // launch 4: output projection (fp32 out, weight plane 4)
    BiasPack bpo;
    bpo.p[0] = o_b; bpo.p[1] = bpo.p[2] = bpo.p[3] = nullptr;
    dim3 gGo(QKV / 128, MROWS / 128, 1);
    gemm_f16<float><<<gGo, 256, GSMEM_T>>>(ga1, gwall + 4*WPLANE, bpo, out);
}

// round 17
// speedup vs baseline: 1.2595x; 1.0014x over previous
#include <cuda_runtime.h>
#include <cuda_fp16.h>
#include <math.h>
#include <stdint.h>

#define NHEADS 16
#define HDIM   128
#define CHUNK  64
#define BATCH  4
#define SEQ    4096
#define HID    2048
#define MROWS  (BATCH*SEQ)            /* 16384 */
#define QKV    (NHEADS*HDIM)          /* 2048  */
#define WPLANE ((size_t)QKV*HID)
#define CPLANE ((size_t)MROWS*QKV)

// ---------------- scratch (device globals; no allocation allowed) -----------
static __device__ __half g_proj[4*CPLANE];            // q,k,v,og planes
static __device__ float  g_beta[(size_t)MROWS*NHEADS];
static __device__ __half g_a1 [(size_t)MROWS*HID];    // fp16 activations
static __device__ __half g_wall[5*WPLANE];            // qw,kw,vw,ogw,ow planes

struct BiasPack { const float* p[4]; };

// ---------------- PTX helpers (family-PTX-safe: sm_80/90-era only) ----------
__device__ __forceinline__ uint32_t smem_u32(const void* p) {
    uint32_t a;
    asm("{ .reg .u64 t; cvta.to.shared.u64 t, %1; cvt.u32.u64 %0, t; }"
        : "=r"(a) : "l"(p));
    return a;
}
__device__ __forceinline__ void cpa16(uint32_t d, const void* s) {
    asm volatile("cp.async.cg.shared.global [%0], [%1], 16;" :: "r"(d), "l"(s));
}
__device__ __forceinline__ void mbar_init(uint32_t a, uint32_t cnt) {
    asm volatile("mbarrier.init.shared.b64 [%0], %1;" :: "r"(a), "r"(cnt) : "memory");
}
__device__ __forceinline__ void mbar_arrive(uint32_t a) {
    asm volatile("mbarrier.arrive.shared.b64 _, [%0];" :: "r"(a) : "memory");
}
__device__ __forceinline__ void mbar_wait(uint32_t a, uint32_t par) {
    asm volatile(
        "{\n\t.reg .pred P;\n\t"
        "W%=:\n\t"
        "mbarrier.try_wait.parity.shared.b64 P, [%0], %1, 0x989680;\n\t"
        "@!P bra W%=;\n\t}"
        :: "r"(a), "r"(par) : "memory");
}
__device__ __forceinline__ void cpa_mbar_arrive(uint32_t a) {
    asm volatile("cp.async.mbarrier.arrive.noinc.shared.b64 [%0];"
                 :: "r"(a) : "memory");
}
__device__ __forceinline__ void ldsm4(uint32_t& r0, uint32_t& r1,
                                      uint32_t& r2, uint32_t& r3, uint32_t a) {
    asm volatile("ldmatrix.sync.aligned.m8n8.x4.shared.b16 {%0,%1,%2,%3}, [%4];"
                 : "=r"(r0), "=r"(r1), "=r"(r2), "=r"(r3) : "r"(a));
}
__device__ __forceinline__ void ldsm4t(uint32_t& r0, uint32_t& r1,
                                       uint32_t& r2, uint32_t& r3, uint32_t a) {
    asm volatile("ldmatrix.sync.aligned.m8n8.x4.trans.shared.b16 {%0,%1,%2,%3}, [%4];"
                 : "=r"(r0), "=r"(r1), "=r"(r2), "=r"(r3) : "r"(a));
}
__device__ __forceinline__ void mma16816(float* c, const uint32_t* a,
                                         uint32_t b0, uint32_t b1) {
    asm volatile(
        "mma.sync.aligned.m16n8k16.row.col.f32.f16.f16.f32 "
        "{%0,%1,%2,%3}, {%4,%5,%6,%7}, {%8,%9}, {%0,%1,%2,%3};"
        : "+f"(c[0]), "+f"(c[1]), "+f"(c[2]), "+f"(c[3])
        : "r"(a[0]), "r"(a[1]), "r"(a[2]), "r"(a[3]), "r"(b0), "r"(b1));
}

__device__ __forceinline__ void st2(float* p, float x, float y) {
    *(float2*)p = make_float2(x, y);
}
__device__ __forceinline__ void st2(__half* p, float x, float y) {
    *(__half2*)p = __floats2half2_rn(x, y);
}
__device__ __forceinline__ uint2 pack4h(float x, float y, float z, float w) {
    __half2 a = __floats2half2_rn(x, y);
    __half2 b = __floats2half2_rn(z, w);
    uint2 r;
    r.x = *(uint32_t*)&a;
    r.y = *(uint32_t*)&b;
    return r;
}

// ---------------------------------------------------------------------------
// mma.sync fp16 GEMM (R15): 128x128 CTA tile, 256 thr, 3-stage mbarrier flow,
// 2 CTAs/SM, grid.z selects weight/bias/output plane.
// ---------------------------------------------------------------------------
#define NSC        32
#define OFF_A      0
#define OFF_W      16384
#define STG_BYTES  32768
#define GSMEM_DATA (3*STG_BYTES)
#define MB_FULL(s)  (GSMEM_DATA + (s)*8)
#define MB_EMPTY(s) (GSMEM_DATA + 24 + (s)*8)
#define GSMEM_T    (GSMEM_DATA + 48)

template <typename OutT>
__global__ __launch_bounds__(256, 2)
void gemm_f16(const __half* __restrict__ A, const __half* __restrict__ Wall,
              BiasPack bp, OutT* __restrict__ Call)
{
    extern __shared__ __align__(1024) char smem[];
    const uint32_t sb = smem_u32(smem);
    const int tid = threadIdx.x;
    const int z   = blockIdx.z;
    const int bn0 = blockIdx.x * 128;
    const int bm0 = blockIdx.y * 128;
    const __half* W = Wall + (size_t)z * WPLANE;
    OutT* C = Call + (size_t)z * CPLANE;
    const float* bias = bp.p[z];
    const size_t rowHB = (size_t)HID * 2;

    if (tid == 0) {
#pragma unroll
        for (int s = 0; s < 3; s++) {
            mbar_init(sb + MB_FULL(s), 256);
            mbar_init(sb + MB_EMPTY(s), 256);
        }
    }
    __syncthreads();

    const int r0  = tid >> 3;
    const int c16 = (tid & 7) * 16;
    const char* abase = (const char*)A + (size_t)bm0 * rowHB + c16;
    const char* wbase = (const char*)W + (size_t)bn0 * rowHB + c16;

    auto load_stage = [&](int sc, int s) {
        const uint32_t st = sb + s * STG_BYTES;
        const char* ap = abase + (size_t)sc * 128;
        const char* wp = wbase + (size_t)sc * 128;
#pragma unroll
        for (int i = 0; i < 4; i++) {
            const int row = r0 + i * 32;
            uint32_t off = (uint32_t)row * 128 + (uint32_t)c16;
            uint32_t sw  = off ^ ((off >> 3) & 0x70);
            cpa16(st + OFF_A + sw, ap + (size_t)row * rowHB);
            cpa16(st + OFF_W + sw, wp + (size_t)row * rowHB);
        }
        cpa_mbar_arrive(sb + MB_FULL(s));
    };

    const int lane = tid & 31;
    const int warp = tid >> 5;
    const int wm = warp >> 2;
    const int wn = warp & 3;

    const int a_row  = wm * 64 + (lane & 15);
    const int a_sel  = (lane >> 4) * 16;
    const uint32_t a_x = (uint32_t)((a_row & 7) << 4);
    const int b_row  = wn * 32 + ((lane >> 4) << 3) + (lane & 7);
    const int b_sel  = ((lane >> 3) & 1) * 16;
    const uint32_t b_x = (uint32_t)((b_row & 7) << 4);

    float acc[4][4][4];
#pragma unroll
    for (int i = 0; i < 4; i++)
#pragma unroll
        for (int j = 0; j < 4; j++)
#pragma unroll
            for (int r = 0; r < 4; r++) acc[i][j][r] = 0.0f;

    load_stage(0, 0);
    load_stage(1, 1);

    for (int sc = 0; sc < NSC; sc++) {
        const int s = sc - (sc / 3) * 3;
        const int u = sc / 3;
        mbar_wait(sb + MB_FULL(s), u & 1);

        const uint32_t st = sb + s * STG_BYTES;
#pragma unroll
        for (int ks = 0; ks < 4; ks++) {
            const uint32_t kb = (uint32_t)(ks * 32);
            uint32_t b[2][4];
#pragma unroll
            for (int nb = 0; nb < 2; nb++) {
                uint32_t broff = (uint32_t)(b_row + nb * 16) * 128
                               + ((kb + (uint32_t)b_sel) ^ b_x);
                ldsm4(b[nb][0], b[nb][1], b[nb][2], b[nb][3], st + OFF_W + broff);
            }
#pragma unroll
            for (int mf = 0; mf < 4; mf++) {
                uint32_t aroff = (uint32_t)(a_row + mf * 16) * 128
                               + ((kb + (uint32_t)a_sel) ^ a_x);
                uint32_t a[4];
                ldsm4(a[0], a[1], a[2], a[3], st + OFF_A + aroff);
                mma16816(acc[mf][0], a, b[0][0], b[0][1]);
                mma16816(acc[mf][1], a, b[0][2], b[0][3]);
                mma16816(acc[mf][2], a, b[1][0], b[1][1]);
                mma16816(acc[mf][3], a, b[1][2], b[1][3]);
            }
        }
        mbar_arrive(sb + MB_EMPTY(s));

        const int sl = sc + 2;
        if (sl < NSC) {
            const int s2 = sl - (sl / 3) * 3;
            const int u2 = sl / 3;
            if (sl >= 3) mbar_wait(sb + MB_EMPTY(s2), (u2 - 1) & 1);
            load_stage(sl, s2);
        }
    }

#pragma unroll
    for (int nf = 0; nf < 4; nf++) {
        const int col = bn0 + wn * 32 + nf * 8 + (lane & 3) * 2;
        float b0 = 0.0f, b1 = 0.0f;
        if (bias) { b0 = bias[col]; b1 = bias[col + 1]; }
#pragma unroll
        for (int mf = 0; mf < 4; mf++) {
            const int row = bm0 + wm * 64 + mf * 16 + (lane >> 2);
            st2(C + (size_t)row * QKV + col,       acc[mf][nf][0] + b0,
                                                   acc[mf][nf][1] + b1);
            st2(C + (size_t)(row + 8) * QKV + col, acc[mf][nf][2] + b0,
                                                   acc[mf][nf][3] + b1);
        }
    }
}

// ---------------------------------------------------------------------------
// prep: ONE launch doing beta GEMM (+fp16 hs copy) AND all 5 weight converts.
// blockIdx.x < 2048            -> beta part (8 warps/block, 1 row/warp)
// blockIdx.x in [2048, 22528)  -> weight convert (plane = idx/4096)
// ---------------------------------------------------------------------------
#define PREP_BETA_BLKS (MROWS/8)          /* 2048 */
#define PREP_W_BLKS    (5*4096)           /* 20480 */

__global__ __launch_bounds__(256)
void prep_kernel(const float* __restrict__ hs, const float* __restrict__ bw,
                 const float* __restrict__ bb, float* __restrict__ beta,
                 __half* __restrict__ a16,
                 const float* __restrict__ w0, const float* __restrict__ w1,
                 const float* __restrict__ w2, const float* __restrict__ w3,
                 const float* __restrict__ w4, __half* __restrict__ wall)
{
    if (blockIdx.x < PREP_BETA_BLKS) {
        int warp = blockIdx.x * 8 + (threadIdx.x >> 5);
        int lane = threadIdx.x & 31;
        const float* x = hs + (size_t)warp * HID;
        __half* xo = a16 + (size_t)warp * HID;

        float acc[NHEADS];
#pragma unroll
        for (int j = 0; j < NHEADS; j++) acc[j] = 0.0f;

        for (int t = 0; t < HID / 128; t++) {
            int k = t * 128 + lane * 4;
            float4 xv = *(const float4*)(x + k);
            *(uint2*)(xo + k) = pack4h(xv.x, xv.y, xv.z, xv.w);
#pragma unroll
            for (int j = 0; j < NHEADS; j++) {
                float4 wv = *(const float4*)(bw + (size_t)j * HID + k);
                acc[j] += xv.x*wv.x + xv.y*wv.y + xv.z*wv.z + xv.w*wv.w;
            }
        }
#pragma unroll
        for (int j = 0; j < NHEADS; j++)
#pragma unroll
            for (int off = 16; off > 0; off >>= 1)
                acc[j] += __shfl_xor_sync(0xffffffffu, acc[j], off);

        if (lane < NHEADS) {
            float v = 0.0f;
#pragma unroll
            for (int j = 0; j < NHEADS; j++) if (lane == j) v = acc[j];
            beta[(size_t)warp * NHEADS + lane] = v + bb[lane];
        }
    } else {
        unsigned idx = blockIdx.x - PREP_BETA_BLKS;
        unsigned plane = idx >> 12;          // /4096
        unsigned blk   = idx & 4095;
        const float* in =
            (plane == 0) ? w0 : (plane == 1) ? w1 :
            (plane == 2) ? w2 : (plane == 3) ? w3 : w4;
        __half* outp = wall + (size_t)plane * WPLANE;
        size_t i = ((size_t)blk * 256 + threadIdx.x) * 4;
        float4 v = *(const float4*)(in + i);
        *(uint2*)(outp + i) = pack4h(v.x, v.y, v.z, v.w);
    }
}

// ---------------------------------------------------------------------------
// Chunk attention v4: HMMA phase-2 and phase-3 as in R16, but the gated
// epilogue is restructured: O staged fp32 in smem (arithmetic IDENTICAL),
// then a row-per-warp pass with fully coalesced og reads / outa writes.
// ---------------------------------------------------------------------------
#define ATT_KS     17408
#define ATT_FQ     34816
#define ATT_FK     35072
#define ATT_S16    35328
#define SROW_B     144
#define ATT_SMEM   (ATT_S16 + 64*SROW_B)   /* 44544 */
#define QROW_B     272
#define OROW_F     132                     /* O stage row stride (floats) */

__global__ __launch_bounds__(256)
void attn_kernel(const __half* __restrict__ q, const __half* __restrict__ k,
                 const __half* __restrict__ v, const __half* __restrict__ og,
                 const float* __restrict__ beta, __half* __restrict__ outa)
{
    extern __shared__ __align__(1024) char smraw[];
    float* fq  = (float*)(smraw + ATT_FQ);
    float* fk  = (float*)(smraw + ATT_FK);
    float* Os  = (float*)smraw;            // O stage: 64 x OROW_F (after GV)
    const uint32_t qsB  = smem_u32(smraw);
    const uint32_t ksB  = qsB + ATT_KS;
    const uint32_t s16B = qsB + ATT_S16;

    const int h  = blockIdx.x;
    const int cn = blockIdx.y;
    const int b  = blockIdx.z;
    const int tid = threadIdx.x;
    const int lane = tid & 31;
    const int warp = tid >> 5;

    const size_t tok0 = (size_t)b * SEQ + (size_t)cn * CHUNK;
    const size_t base = (tok0 * NHEADS + h) * HDIM;
    const int tokstride = NHEADS * HDIM;
    const float eps_n = 1.1313708499e-11f;

    // ---- phase 1: raw fp16 q,k to padded smem; 1/norm via warp reduce ----
    for (int f = tid; f < 64 * 32; f += 256) {
        int row = f >> 5;
        int l8  = f & 31;
        size_t g = base + (size_t)row * tokstride + l8 * 4;
        uint2 qr = *(const uint2*)(q + g);
        uint2 kr = *(const uint2*)(k + g);

        float2 q01 = __half22float2(*(__half2*)&qr.x);
        float2 q23 = __half22float2(*(__half2*)&qr.y);
        float2 k01 = __half22float2(*(__half2*)&kr.x);
        float2 k23 = __half22float2(*(__half2*)&kr.y);
        float sq = q01.x*q01.x + q01.y*q01.y + q23.x*q23.x + q23.y*q23.y;
        float sk = k01.x*k01.x + k01.y*k01.y + k23.x*k23.x + k23.y*k23.y;
#pragma unroll
        for (int off = 16; off > 0; off >>= 1) {
            sq += __shfl_xor_sync(0xffffffffu, sq, off);
            sk += __shfl_xor_sync(0xffffffffu, sk, off);
        }
        *(uint2*)(smraw + row * QROW_B + l8 * 8)          = qr;
        *(uint2*)(smraw + ATT_KS + row * QROW_B + l8 * 8) = kr;
        if (lane == 0) {
            fq[row] = 1.0f / fmaxf(sqrtf(sq), eps_n);
            fk[row] = 1.0f / fmaxf(sqrtf(sk), eps_n);
        }
    }
    __syncthreads();

    // ---- phase 2: S16 = tril( (q.k) * fq_i * fk_j ) via HMMA, fp16 out ----
    {
        const int m0 = (warp >> 1) * 16;
        const int n0 = (warp & 1) * 32;
        if (n0 > m0 + 15) {
            for (int idx = lane; idx < 256; idx += 32) {
                int r  = m0 + (idx >> 4);
                int jp = n0 + (idx & 15) * 2;
                *(uint32_t*)(smraw + ATT_S16 + r * SROW_B + jp * 2) = 0u;
            }
        } else {
            float acc[4][4];
#pragma unroll
            for (int t = 0; t < 4; t++)
#pragma unroll
                for (int r = 0; r < 4; r++) acc[t][r] = 0.0f;

            const uint32_t aoff = qsB + (uint32_t)(m0 + (lane & 15)) * QROW_B
                                + (uint32_t)((lane >> 4) * 16);
            const int brow = n0 + ((lane >> 4) << 3) + (lane & 7);
            const uint32_t boff0 = ksB + (uint32_t)brow * QROW_B
                                 + (uint32_t)(((lane >> 3) & 1) * 16);
            const uint32_t boff1 = boff0 + 16u * QROW_B;

#pragma unroll
            for (int ks = 0; ks < 8; ks++) {
                const uint32_t kb = (uint32_t)(ks * 32);
                uint32_t a[4], b0[4], b1[4];
                ldsm4(a[0], a[1], a[2], a[3], aoff + kb);
                ldsm4(b0[0], b0[1], b0[2], b0[3], boff0 + kb);
                ldsm4(b1[0], b1[1], b1[2], b1[3], boff1 + kb);
                mma16816(acc[0], a, b0[0], b0[1]);
                mma16816(acc[1], a, b0[2], b0[3]);
                mma16816(acc[2], a, b1[0], b1[1]);
                mma16816(acc[3], a, b1[2], b1[3]);
            }

            const int r0s = m0 + (lane >> 2);
            const int r1s = r0s + 8;
            const float fq0 = fq[r0s], fq1 = fq[r1s];
#pragma unroll
            for (int t = 0; t < 4; t++) {
                const int j0 = n0 + t * 8 + (lane & 3) * 2;
                const int j1 = j0 + 1;
                const float fk0 = fk[j0], fk1 = fk[j1];
                float v00 = (j0 <= r0s) ? acc[t][0] * fq0 * fk0 : 0.0f;
                float v01 = (j1 <= r0s) ? acc[t][1] * fq0 * fk1 : 0.0f;
                float v10 = (j0 <= r1s) ? acc[t][2] * fq1 * fk0 : 0.0f;
                float v11 = (j1 <= r1s) ? acc[t][3] * fq1 * fk1 : 0.0f;
                *(__half2*)(smraw + ATT_S16 + r0s * SROW_B + j0 * 2) =
                    __floats2half2_rn(v00, v01);
                *(__half2*)(smraw + ATT_S16 + r1s * SROW_B + j0 * 2) =
                    __floats2half2_rn(v10, v11);
            }
        }
    }
    __syncthreads();   // S16 complete; qT ldsm reads done

    // ---- gv = softplus(beta) * v, fp16, into the qT region [j][kk] ----
    for (int f = tid; f < 64 * 32; f += 256) {
        int row = f >> 5;
        int l8  = f & 31;
        float bta = beta[(tok0 + row) * NHEADS + h];
        float sp  = (bta > 20.0f) ? bta : log1pf(expf(bta));
        uint2 vr = *(const uint2*)(v + base + (size_t)row * tokstride + l8 * 4);
        float2 v01 = __half22float2(*(__half2*)&vr.x);
        float2 v23 = __half22float2(*(__half2*)&vr.y);
        *(uint2*)(smraw + row * QROW_B + l8 * 8) =
            pack4h(v01.x * sp, v01.y * sp, v23.x * sp, v23.y * sp);
    }
    __syncthreads();

    // ---- phase 3: O = S16 @ GV via HMMA; stage O fp32 to smem ----
    {
        const int mt = warp >> 1;
        const int nh = warp & 1;
        float acc[8][4];
#pragma unroll
        for (int f = 0; f < 8; f++)
#pragma unroll
            for (int r = 0; r < 4; r++) acc[f][r] = 0.0f;

        for (int kst = 0; kst <= mt; kst++) {
            uint32_t a[4];
            uint32_t aaddr = s16B + (uint32_t)(16*mt + (lane & 15)) * SROW_B
                           + (uint32_t)(kst * 32 + (lane >> 4) * 16);
            ldsm4(a[0], a[1], a[2], a[3], aaddr);
#pragma unroll
            for (int g = 0; g < 4; g++) {
                const uint32_t brow = (uint32_t)(kst * 16
                                   + ((lane >> 3) & 1) * 8 + (lane & 7));
                const uint32_t bcol = (uint32_t)(nh * 64 + g * 16
                                   + (lane >> 4) * 8);
                uint32_t b[4];
                ldsm4t(b[0], b[1], b[2], b[3], qsB + brow * QROW_B + bcol * 2);
                mma16816(acc[g*2],   a, b[0], b[1]);
                mma16816(acc[g*2+1], a, b[2], b[3]);
            }
        }

        __syncthreads();   // all GV ldsm reads done; qT/kT region reusable

        const int r0o = 16*mt + (lane >> 2);
        const int r1o = r0o + 8;
#pragma unroll
        for (int f = 0; f < 8; f++) {
            const int col = nh * 64 + (f >> 1) * 16 + (f & 1) * 8
                          + (lane & 3) * 2;
            *(float2*)&Os[r0o * OROW_F + col] = make_float2(acc[f][0], acc[f][1]);
            *(float2*)&Os[r1o * OROW_F + col] = make_float2(acc[f][2], acc[f][3]);
        }
    }
    __syncthreads();

    // ---- coalesced gated epilogue: y = O * silu(og), fp16 out ----
    for (int f = tid; f < 64 * 32; f += 256) {
        int row = f >> 5;
        int l4  = (f & 31) * 4;
        float4 o4 = *(const float4*)&Os[row * OROW_F + l4];
        size_t off = base + (size_t)row * tokstride + l4;
        uint2 gr = *(const uint2*)(og + off);
        float2 g01 = __half22float2(*(__half2*)&gr.x);
        float2 g23 = __half22float2(*(__half2*)&gr.y);
        float y0 = o4.x * (g01.x / (1.0f + expf(-g01.x)));
        float y1 = o4.y * (g01.y / (1.0f + expf(-g01.y)));
        float y2 = o4.z * (g23.x / (1.0f + expf(-g23.x)));
        float y3 = o4.w * (g23.y / (1.0f + expf(-g23.y)));
        *(uint2*)(outa + off) = pack4h(y0, y1, y2, y3);
    }
}

// ---------------------------------------------------------------------------
extern "C" void kernel_launch(void* const* d_in, const int* in_sizes, int n_in,
                              void* d_out, int out_size)
{
    const float* hs   = (const float*)d_in[0];
    const float* q_w  = (const float*)d_in[1];
    const float* q_b  = (const float*)d_in[2];
    const float* k_w  = (const float*)d_in[3];
    const float* k_b  = (const float*)d_in[4];
    const float* v_w  = (const float*)d_in[5];
    const float* v_b  = (const float*)d_in[6];
    /* a_w, a_b (d_in[7], d_in[8]) are dead code in the reference */
    const float* b_w  = (const float*)d_in[9];
    const float* b_b  = (const float*)d_in[10];
    const float* og_w = (const float*)d_in[11];
    const float* o_w  = (const float*)d_in[12];
    const float* o_b  = (const float*)d_in[13];
    float* out = (float*)d_out;

    float *gbeta;
    __half *gproj, *ga1, *gwall;
    cudaGetSymbolAddress((void**)&gproj, g_proj);
    cudaGetSymbolAddress((void**)&gbeta, g_beta);
    cudaGetSymbolAddress((void**)&ga1,   g_a1);
    cudaGetSymbolAddress((void**)&gwall, g_wall);

    cudaFuncSetAttribute(gemm_f16<__half>,
                         cudaFuncAttributeMaxDynamicSharedMemorySize, GSMEM_T);
    cudaFuncSetAttribute(gemm_f16<float>,
                         cudaFuncAttributeMaxDynamicSharedMemorySize, GSMEM_T);
    cudaFuncSetAttribute(attn_kernel,
                         cudaFuncAttributeMaxDynamicSharedMemorySize, ATT_SMEM);

    // launch 0: beta GEMM + fp16 activation convert + all 5 weight converts
    prep_kernel<<<PREP_BETA_BLKS + PREP_W_BLKS, 256>>>(
        hs, b_w, b_b, gbeta, ga1, q_w, k_w, v_w, og_w, o_w, gwall);

    // launch 1: all 4 projection GEMMs in one launch (grid.z = plane)
    BiasPack bp4;
    bp4.p[0] = q_b; bp4.p[1] = k_b; bp4.p[2] = v_b; bp4.p[3] = nullptr;
    dim3 gG4(QKV / 128, MROWS / 128, 4);
    gemm_f16<__half><<<gG4, 256, GSMEM_T>>>(ga1, gwall, bp4, gproj);

    // launch 2: fused attention (HMMA phase-2 AND phase-3, staged epilogue)
    dim3 gAttn(NHEADS, SEQ / CHUNK, BATCH);
    attn_kernel<<<gAttn, 256, ATT_SMEM>>>(gproj,              // q plane
                                          gproj + CPLANE,     // k plane
                                          gproj + 2*CPLANE,   // v plane
                                          gproj + 3*CPLANE,   // og plane
                                          gbeta, ga1);

    // launch 3: output projection (fp32 out, weight plane 4)
    BiasPack bpo;
    bpo.p[0] = o_b; bpo.p[1] = bpo.p[2] = bpo.p[3] = nullptr;
    dim3 gGo(QKV / 128, MROWS / 128, 1);
    gemm_f16<float><<<gGo, 256, GSMEM_T>>>(ga1, gwall + 4*WPLANE, bpo, out);
}